// round 12
// baseline (speedup 1.0000x reference)
#include <cuda_runtime.h>
#include <cuda_bf16.h>
#include <stdint.h>
#include <cstdint>
#include <math.h>

#define NROWS 16384
#define DMODEL 1024
#define DFF 4096
#define TOPK 512

// Scratch (device globals)
__device__ float g_xn[(size_t)NROWS * DMODEL];
__device__ float g_h [(size_t)NROWS * DMODEL];
__device__ float g_sc[(size_t)NROWS * DFF];
__device__ float g_z [(size_t)NROWS * DFF];
__device__ __nv_bfloat16 g_xh [(size_t)NROWS * DMODEL];
__device__ __nv_bfloat16 g_xl [(size_t)NROWS * DMODEL];
__device__ __nv_bfloat16 g_hh [(size_t)NROWS * DMODEL];
__device__ __nv_bfloat16 g_hl [(size_t)NROWS * DMODEL];
__device__ __nv_bfloat16 g_w1h[(size_t)DFF * DMODEL];
__device__ __nv_bfloat16 g_w1l[(size_t)DFF * DMODEL];
__device__ __nv_bfloat16 g_w2h[(size_t)DMODEL * DFF];
__device__ __nv_bfloat16 g_w2l[(size_t)DMODEL * DFF];
__device__ __nv_bfloat16 g_wr2h[(size_t)DFF * DMODEL];
__device__ __nv_bfloat16 g_zh [(size_t)NROWS * DFF];
__device__ __nv_bfloat16 g_zl [(size_t)NROWS * DFF];

// ---------------------------------------------------------------------------
// XLA f32 erf polynomial, uncontracted
// ---------------------------------------------------------------------------
__device__ __forceinline__ float erf_xla(float xin) {
    float x = fminf(fmaxf(xin, -4.0f), 4.0f);
    float x2 = __fmul_rn(x, x);
    float p = -2.72614225801306e-10f;
    p = __fadd_rn(__fmul_rn(p, x2),  2.77068142495902e-08f);
    p = __fadd_rn(__fmul_rn(p, x2), -2.10102402082508e-06f);
    p = __fadd_rn(__fmul_rn(p, x2), -5.69250639462346e-05f);
    p = __fadd_rn(__fmul_rn(p, x2), -7.34990630326855e-04f);
    p = __fadd_rn(__fmul_rn(p, x2), -2.95459980854025e-03f);
    p = __fadd_rn(__fmul_rn(p, x2), -1.60960333262415e-02f);
    float q = -1.45660718464996e-05f;
    q = __fadd_rn(__fmul_rn(q, x2), -2.13374055278905e-04f);
    q = __fadd_rn(__fmul_rn(q, x2), -1.68282697438203e-03f);
    q = __fadd_rn(__fmul_rn(q, x2), -7.37332916720468e-03f);
    q = __fadd_rn(__fmul_rn(q, x2), -1.42647390514189e-02f);
    return __fdiv_rn(__fmul_rn(x, p), q);
}

__device__ __forceinline__ float gelu_f(float v) {
    float t = __fdiv_rn(v, 1.41421356237309504880f);
    float e = erf_xla(t);
    return __fmul_rn(__fmul_rn(v, __fadd_rn(e, 1.0f)), 0.5f);
}

// ---------------------------------------------------------------------------
// LayerNorm (unchanged, passing)
// ---------------------------------------------------------------------------
__global__ void __launch_bounds__(256) ln_kernel(
    const float* __restrict__ x, const float* __restrict__ g,
    const float* __restrict__ b, float* __restrict__ o)
{
    __shared__ double red[8];
    __shared__ float s_mu, s_inv;
    const int row = blockIdx.x;
    const int tid = threadIdx.x;
    const float4* xr = (const float4*)(x + (size_t)row * DMODEL);
    float4* orow = (float4*)(o + (size_t)row * DMODEL);

    float4 v = xr[tid];

    double s = (double)v.x + (double)v.y + (double)v.z + (double)v.w;
    #pragma unroll
    for (int off = 16; off; off >>= 1) s += __shfl_down_sync(0xffffffffu, s, off);
    if ((tid & 31) == 0) red[tid >> 5] = s;
    __syncthreads();
    if (tid == 0) {
        double S = 0.0;
        #pragma unroll
        for (int w = 0; w < 8; w++) S += red[w];
        s_mu = (float)(S * (1.0 / DMODEL));
    }
    __syncthreads();
    const float mu = s_mu;
    __syncthreads();

    float dx0 = __fsub_rn(v.x, mu), dx1 = __fsub_rn(v.y, mu);
    float dx2 = __fsub_rn(v.z, mu), dx3 = __fsub_rn(v.w, mu);
    double ss = (double)__fmul_rn(dx0, dx0) + (double)__fmul_rn(dx1, dx1)
              + (double)__fmul_rn(dx2, dx2) + (double)__fmul_rn(dx3, dx3);
    #pragma unroll
    for (int off = 16; off; off >>= 1) ss += __shfl_down_sync(0xffffffffu, ss, off);
    if ((tid & 31) == 0) red[tid >> 5] = ss;
    __syncthreads();
    if (tid == 0) {
        double SS = 0.0;
        #pragma unroll
        for (int w = 0; w < 8; w++) SS += red[w];
        float var = (float)(SS * (1.0 / DMODEL));
        s_inv = (float)(1.0 / sqrt((double)__fadd_rn(var, 1e-5f)));
    }
    __syncthreads();
    const float inv = s_inv;
    const float4 gv = ((const float4*)g)[tid];
    const float4 bv = ((const float4*)b)[tid];
    float4 r;
    r.x = __fadd_rn(__fmul_rn(__fmul_rn(dx0, inv), gv.x), bv.x);
    r.y = __fadd_rn(__fmul_rn(__fmul_rn(dx1, inv), gv.y), bv.y);
    r.z = __fadd_rn(__fmul_rn(__fmul_rn(dx2, inv), gv.z), bv.z);
    r.w = __fadd_rn(__fmul_rn(__fmul_rn(dx3, inv), gv.w), bv.w);
    orow[tid] = r;
}

// ---------------------------------------------------------------------------
// fp32 -> bf16 hi/lo split
// ---------------------------------------------------------------------------
union bfu { __nv_bfloat162 b; unsigned int u; };

__device__ __forceinline__ void split2(float a, float b, unsigned int& hi, unsigned int& lo) {
    __nv_bfloat16 h0 = __float2bfloat16_rn(a);
    __nv_bfloat16 h1 = __float2bfloat16_rn(b);
    __nv_bfloat16 l0 = __float2bfloat16_rn(__fsub_rn(a, __bfloat162float(h0)));
    __nv_bfloat16 l1 = __float2bfloat16_rn(__fsub_rn(b, __bfloat162float(h1)));
    bfu H; H.b = __nv_bfloat162(h0, h1); hi = H.u;
    bfu L; L.b = __nv_bfloat162(l0, l1); lo = L.u;
}

__global__ void __launch_bounds__(256) split_bf16_kernel(
    const float* __restrict__ src, __nv_bfloat16* __restrict__ hi,
    __nv_bfloat16* __restrict__ lo, size_t n4)
{
    size_t i = (size_t)blockIdx.x * 256 + threadIdx.x;
    size_t stride = (size_t)gridDim.x * 256;
    for (; i < n4; i += stride) {
        float4 v = ((const float4*)src)[i];
        uint2 H, L;
        split2(v.x, v.y, H.x, L.x);
        split2(v.z, v.w, H.y, L.y);
        ((uint2*)hi)[i] = H;
        ((uint2*)lo)[i] = L;
    }
}

// hi-only split (Wr2: 2-term scores need no B-lo)
__global__ void __launch_bounds__(256) split_bf16_hi_kernel(
    const float* __restrict__ src, __nv_bfloat16* __restrict__ hi, size_t n4)
{
    size_t i = (size_t)blockIdx.x * 256 + threadIdx.x;
    size_t stride = (size_t)gridDim.x * 256;
    for (; i < n4; i += stride) {
        float4 v = ((const float4*)src)[i];
        bfu a, b;
        a.b = __nv_bfloat162(__float2bfloat16_rn(v.x), __float2bfloat16_rn(v.y));
        b.b = __nv_bfloat162(__float2bfloat16_rn(v.z), __float2bfloat16_rn(v.w));
        uint2 H; H.x = a.u; H.y = b.u;
        ((uint2*)hi)[i] = H;
    }
}

// ---------------------------------------------------------------------------
// mma / ldmatrix / cp.async primitives
// ---------------------------------------------------------------------------
__device__ __forceinline__ void mma16_bf16(float c[4], const unsigned int a[4],
                                           const unsigned int b[2]) {
    asm volatile("mma.sync.aligned.m16n8k16.row.col.f32.bf16.bf16.f32 "
        "{%0,%1,%2,%3}, {%4,%5,%6,%7}, {%8,%9}, {%0,%1,%2,%3};\n"
        : "+f"(c[0]), "+f"(c[1]), "+f"(c[2]), "+f"(c[3])
        : "r"(a[0]), "r"(a[1]), "r"(a[2]), "r"(a[3]), "r"(b[0]), "r"(b[1]));
}
__device__ __forceinline__ void ldsm4(unsigned int& r0, unsigned int& r1,
                                      unsigned int& r2, unsigned int& r3,
                                      const void* p) {
    unsigned int a = (unsigned int)__cvta_generic_to_shared(p);
    asm volatile("ldmatrix.sync.aligned.m8n8.x4.shared.b16 {%0,%1,%2,%3}, [%4];"
                 : "=r"(r0), "=r"(r1), "=r"(r2), "=r"(r3) : "r"(a));
}
__device__ __forceinline__ void cpa16(void* s, const void* g) {
    unsigned int a = (unsigned int)__cvta_generic_to_shared(s);
    asm volatile("cp.async.cg.shared.global [%0], [%1], 16;\n"
                 :: "r"(a), "l"(g) : "memory");
}
__device__ __forceinline__ void cpa_commit() {
    asm volatile("cp.async.commit_group;\n" ::: "memory");
}
template <int N>
__device__ __forceinline__ void cpa_wait() {
    asm volatile("cp.async.wait_group %0;\n" :: "n"(N) : "memory");
}

// ---------------------------------------------------------------------------
// bf16 3-term GEMM body (ldmatrix + cp.async, 3-stage) — UNCHANGED, passing.
// ---------------------------------------------------------------------------
#define STG_STRIDE 18432
#define TC_DYNSMEM (3 * STG_STRIDE)

__device__ __forceinline__ void issue_chunk(
    char* sm, int st, int k0,
    const __nv_bfloat16* Ag0, const __nv_bfloat16* Ag1, const __nv_bfloat16* Bg,
    int arow, int akb, int brow, int bkb, int boff)
{
    char* base = sm + st * STG_STRIDE;
    cpa16(base + arow * 48 + akb,        Ag0 + k0);
    cpa16(base + 6144 + arow * 48 + akb, Ag1 + k0);
    cpa16(base + boff + brow * 48 + bkb, Bg + k0);
    cpa_commit();
}

__device__ __forceinline__ void gemm_bf16_body(
    const __nv_bfloat16* __restrict__ Ahg, const __nv_bfloat16* __restrict__ Alg,
    const __nv_bfloat16* __restrict__ Bhg, const __nv_bfloat16* __restrict__ Blg,
    float* __restrict__ C, int M, int N, int K, int bx, int by, char* sm)
{
    const int tid  = threadIdx.x;
    const int m0   = by * 128;
    const int n0   = bx * 64;
    const int wid  = tid >> 5;
    const int lane = tid & 31;
    const int gid  = lane >> 2;
    const int tig  = lane & 3;
    const int wm   = (wid & 3) * 32;
    const int wn   = (wid >> 2) * 32;
    const int g8   = lane >> 3;
    const int r8   = lane & 7;

    const int arow = tid >> 1, akb = (tid & 1) * 16, ak = (tid & 1) * 8;
    const int bt = tid & 127;
    const int brow = bt >> 1, bkb = (bt & 1) * 16, bk = (bt & 1) * 8;
    const bool bhi = tid < 128;
    const int boff = bhi ? 12288 : 15360;

    const __nv_bfloat16* Ag0 = Ahg + (size_t)(m0 + arow) * K + ak;
    const __nv_bfloat16* Ag1 = Alg + (size_t)(m0 + arow) * K + ak;
    const __nv_bfloat16* Bg  = (bhi ? Bhg : Blg) + (size_t)(n0 + brow) * K + bk;

    float acc[2][4][4];
    #pragma unroll
    for (int mt = 0; mt < 2; mt++)
        #pragma unroll
        for (int nt = 0; nt < 4; nt++)
            #pragma unroll
            for (int r = 0; r < 4; r++) acc[mt][nt][r] = 0.0f;

    const int a_row = wm + (g8 & 1) * 8 + r8;
    const int a_col = (g8 >> 1) * 16;
    const int b_row = wn + (g8 >> 1) * 8 + r8;
    const int b_col = (g8 & 1) * 16;

    const int NC = K >> 4;
    issue_chunk(sm, 0, 0,  Ag0, Ag1, Bg, arow, akb, brow, bkb, boff);
    issue_chunk(sm, 1, 16, Ag0, Ag1, Bg, arow, akb, brow, bkb, boff);

    for (int i = 0; i < NC; i++) {
        const int st = i % 3;
        if (i + 2 < NC) cpa_wait<1>(); else cpa_wait<0>();
        __syncthreads();
        if (i + 2 < NC)
            issue_chunk(sm, (i + 2) % 3, (i + 2) * 16,
                        Ag0, Ag1, Bg, arow, akb, brow, bkb, boff);

        char* base = sm + st * STG_STRIDE;
        unsigned int afh[2][4], afl[2][4], bfh[4][2], bfl[4][2];
        #pragma unroll
        for (int mt = 0; mt < 2; mt++) {
            const int ro = (a_row + mt * 16) * 48 + a_col;
            ldsm4(afh[mt][0], afh[mt][1], afh[mt][2], afh[mt][3], base + ro);
            ldsm4(afl[mt][0], afl[mt][1], afl[mt][2], afl[mt][3], base + 6144 + ro);
        }
        #pragma unroll
        for (int p = 0; p < 2; p++) {
            const int ro = (b_row + p * 16) * 48 + b_col;
            ldsm4(bfh[p*2][0], bfh[p*2][1], bfh[p*2+1][0], bfh[p*2+1][1],
                  base + 12288 + ro);
            ldsm4(bfl[p*2][0], bfl[p*2][1], bfl[p*2+1][0], bfl[p*2+1][1],
                  base + 15360 + ro);
        }
        #pragma unroll
        for (int mt = 0; mt < 2; mt++)
            #pragma unroll
            for (int nt = 0; nt < 4; nt++) {
                mma16_bf16(acc[mt][nt], afh[mt], bfh[nt]);
                mma16_bf16(acc[mt][nt], afh[mt], bfl[nt]);
                mma16_bf16(acc[mt][nt], afl[mt], bfh[nt]);
            }
    }

    #pragma unroll
    for (int mt = 0; mt < 2; mt++)
        #pragma unroll
        for (int nt = 0; nt < 4; nt++) {
            const int r0 = m0 + wm + mt * 16 + gid;
            const int c0 = n0 + wn + nt * 8 + tig * 2;
            *(float2*)&C[(size_t)r0 * N + c0]       = make_float2(acc[mt][nt][0], acc[mt][nt][1]);
            *(float2*)&C[(size_t)(r0 + 8) * N + c0] = make_float2(acc[mt][nt][2], acc[mt][nt][3]);
        }
}

// ---------------------------------------------------------------------------
// STANDALONE 2-term scores GEMM: C = (Ah + Al) @ Bh^T.  Complete copy —
// shares NO code with the 3-term body.  B-lo absent: B producers are
// threads 0..127 only; B-lo smem region unused.
// ---------------------------------------------------------------------------
__global__ void __launch_bounds__(256) gemm_scores_2t(
    const __nv_bfloat16* __restrict__ Ahg, const __nv_bfloat16* __restrict__ Alg,
    const __nv_bfloat16* __restrict__ Bhg,
    float* __restrict__ C, int M, int N, int K)
{
    extern __shared__ __align__(16) char sm[];
    const int tid  = threadIdx.x;
    const int m0   = (int)blockIdx.y * 128;
    const int n0   = (int)blockIdx.x * 64;
    const int wid  = tid >> 5;
    const int lane = tid & 31;
    const int gid  = lane >> 2;
    const int tig  = lane & 3;
    const int wm   = (wid & 3) * 32;
    const int wn   = (wid >> 2) * 32;
    const int g8   = lane >> 3;
    const int r8   = lane & 7;

    const int arow = tid >> 1, akb = (tid & 1) * 16, ak = (tid & 1) * 8;
    const int bt = tid & 127;
    const int brow = bt >> 1, bkb = (bt & 1) * 16, bk = (bt & 1) * 8;
    const bool bact = tid < 128;

    const __nv_bfloat16* Ag0 = Ahg + (size_t)(m0 + arow) * K + ak;
    const __nv_bfloat16* Ag1 = Alg + (size_t)(m0 + arow) * K + ak;
    const __nv_bfloat16* Bg  = Bhg + (size_t)(n0 + brow) * K + bk;

    float acc[2][4][4];
    #pragma unroll
    for (int mt = 0; mt < 2; mt++)
        #pragma unroll
        for (int nt = 0; nt < 4; nt++)
            #pragma unroll
            for (int r = 0; r < 4; r++) acc[mt][nt][r] = 0.0f;

    const int a_row = wm + (g8 & 1) * 8 + r8;
    const int a_col = (g8 >> 1) * 16;
    const int b_row = wn + (g8 >> 1) * 8 + r8;
    const int b_col = (g8 & 1) * 16;

    const int NC = K >> 4;
    // prologue: stages 0,1
    #pragma unroll
    for (int pr = 0; pr < 2; pr++) {
        char* base = sm + pr * STG_STRIDE;
        cpa16(base + arow * 48 + akb,        Ag0 + pr * 16);
        cpa16(base + 6144 + arow * 48 + akb, Ag1 + pr * 16);
        if (bact) cpa16(base + 12288 + brow * 48 + bkb, Bg + pr * 16);
        cpa_commit();
    }

    for (int i = 0; i < NC; i++) {
        const int st = i % 3;
        if (i + 2 < NC) cpa_wait<1>(); else cpa_wait<0>();
        __syncthreads();
        if (i + 2 < NC) {
            char* nb = sm + ((i + 2) % 3) * STG_STRIDE;
            const int k0 = (i + 2) * 16;
            cpa16(nb + arow * 48 + akb,        Ag0 + k0);
            cpa16(nb + 6144 + arow * 48 + akb, Ag1 + k0);
            if (bact) cpa16(nb + 12288 + brow * 48 + bkb, Bg + k0);
            cpa_commit();
        }

        char* base = sm + st * STG_STRIDE;
        unsigned int afh[2][4], afl[2][4], bfh[4][2];
        #pragma unroll
        for (int mt = 0; mt < 2; mt++) {
            const int ro = (a_row + mt * 16) * 48 + a_col;
            ldsm4(afh[mt][0], afh[mt][1], afh[mt][2], afh[mt][3], base + ro);
            ldsm4(afl[mt][0], afl[mt][1], afl[mt][2], afl[mt][3], base + 6144 + ro);
        }
        #pragma unroll
        for (int p = 0; p < 2; p++) {
            const int ro = (b_row + p * 16) * 48 + b_col;
            ldsm4(bfh[p*2][0], bfh[p*2][1], bfh[p*2+1][0], bfh[p*2+1][1],
                  base + 12288 + ro);
        }
        #pragma unroll
        for (int mt = 0; mt < 2; mt++)
            #pragma unroll
            for (int nt = 0; nt < 4; nt++) {
                mma16_bf16(acc[mt][nt], afh[mt], bfh[nt]);
                mma16_bf16(acc[mt][nt], afl[mt], bfh[nt]);
            }
    }

    #pragma unroll
    for (int mt = 0; mt < 2; mt++)
        #pragma unroll
        for (int nt = 0; nt < 4; nt++) {
            const int r0 = m0 + wm + mt * 16 + gid;
            const int c0 = n0 + wn + nt * 8 + tig * 2;
            *(float2*)&C[(size_t)r0 * N + c0]       = make_float2(acc[mt][nt][0], acc[mt][nt][1]);
            *(float2*)&C[(size_t)(r0 + 8) * N + c0] = make_float2(acc[mt][nt][2], acc[mt][nt][3]);
        }
}

// ---------------------------------------------------------------------------
// fp32 chunked GEMM body for h, with gelu + bf16-split epilogue (unchanged)
// ---------------------------------------------------------------------------
__device__ __forceinline__ void acc_body_h(
    const float* __restrict__ A, const float* __restrict__ B,
    float* __restrict__ C, __nv_bfloat16* __restrict__ Ch,
    __nv_bfloat16* __restrict__ Cl, int M, int N, int K, int bx, int by)
{
    __shared__ float As[8][128];
    __shared__ float Bs[8][64];

    const int m0 = by * 128;
    const int n0 = bx * 64;
    const int tid = threadIdx.x;
    const int lrA = tid >> 1;
    const int lcA = (tid & 1) * 4;
    const int lrB = tid >> 2;
    const int lcB = (tid & 3) * 2;
    const int tx = tid & 15;
    const int ty = tid >> 4;

    const float* Aptr = A + (size_t)(m0 + lrA) * K + lcA;
    const float* Bptr = B + (size_t)(n0 + lrB) * K + lcB;

    float acc[8][4], chk[8][4];
    #pragma unroll
    for (int i = 0; i < 8; i++)
        #pragma unroll
        for (int j = 0; j < 4; j++) { acc[i][j] = 0.0f; chk[i][j] = 0.0f; }

    float4 av = *(const float4*)(Aptr);
    float2 bv = *(const float2*)(Bptr);

    for (int k0 = 0; k0 < K; k0 += 8) {
        As[lcA + 0][lrA] = av.x; As[lcA + 1][lrA] = av.y;
        As[lcA + 2][lrA] = av.z; As[lcA + 3][lrA] = av.w;
        Bs[lcB + 0][lrB] = bv.x; Bs[lcB + 1][lrB] = bv.y;
        __syncthreads();

        if (k0 + 8 < K) {
            av = *(const float4*)(Aptr + k0 + 8);
            bv = *(const float2*)(Bptr + k0 + 8);
        }

        #pragma unroll
        for (int kk = 0; kk < 8; kk++) {
            float4 a0 = *(const float4*)&As[kk][ty * 4];
            float4 a1 = *(const float4*)&As[kk][64 + ty * 4];
            float4 b0 = *(const float4*)&Bs[kk][tx * 4];
            float ar[8] = {a0.x, a0.y, a0.z, a0.w, a1.x, a1.y, a1.z, a1.w};
            float br[4] = {b0.x, b0.y, b0.z, b0.w};
            #pragma unroll
            for (int i = 0; i < 8; i++)
                #pragma unroll
                for (int j = 0; j < 4; j++)
                    chk[i][j] = fmaf(ar[i], br[j], chk[i][j]);
        }
        if ((k0 & 24) == 24) {
            #pragma unroll
            for (int i = 0; i < 8; i++)
                #pragma unroll
                for (int j = 0; j < 4; j++) {
                    acc[i][j] = __fadd_rn(acc[i][j], chk[i][j]);
                    chk[i][j] = 0.0f;
                }
        }
        __syncthreads();
    }

    #pragma unroll
    for (int i = 0; i < 8; i++) {
        const int row = m0 + ((i < 4) ? (ty * 4 + i) : (64 + ty * 4 + i - 4));
        float v0 = gelu_f(acc[i][0]), v1 = gelu_f(acc[i][1]);
        float v2 = gelu_f(acc[i][2]), v3 = gelu_f(acc[i][3]);
        float4 r; r.x = v0; r.y = v1; r.z = v2; r.w = v3;
        *(float4*)(C + (size_t)row * N + n0 + tx * 4) = r;
        unsigned int H0, L0, H1, L1;
        split2(v0, v1, H0, L0);
        split2(v2, v3, H1, L1);
        uint2 H; H.x = H0; H.y = H1;
        uint2 L; L.x = L0; L.y = L1;
        *(uint2*)(Ch + (size_t)row * N + n0 + tx * 4) = H;
        *(uint2*)(Cl + (size_t)row * N + n0 + tx * 4) = L;
    }
}

// ---------------------------------------------------------------------------
// Fused heterogeneous kernel: 1/5 h (fma pipe), 4/5 z (tensor pipe)
// ---------------------------------------------------------------------------
__global__ void __launch_bounds__(256) fused_h_z(
    const float* __restrict__ xn, const float* __restrict__ Wr1,
    float* __restrict__ h, __nv_bfloat16* __restrict__ hh, __nv_bfloat16* __restrict__ hl,
    const __nv_bfloat16* __restrict__ xh, const __nv_bfloat16* __restrict__ xl,
    const __nv_bfloat16* __restrict__ w1h, const __nv_bfloat16* __restrict__ w1l,
    float* __restrict__ z)
{
    extern __shared__ __align__(16) char dynsm[];
    const int bid = blockIdx.x;
    if (bid % 5 == 0) {
        const int sid = bid / 5;
        acc_body_h(xn, Wr1, h, hh, hl, NROWS, DMODEL, DMODEL, sid & 15, sid >> 4);
    } else {
        const int sid = bid - bid / 5 - 1;
        gemm_bf16_body(xh, xl, w1h, w1l, z, NROWS, DFF, DMODEL, sid & 63, sid >> 6, dynsm);
    }
}

__global__ void __launch_bounds__(256) gemm_bt_bf16v2(
    const __nv_bfloat16* __restrict__ Ahg, const __nv_bfloat16* __restrict__ Alg,
    const __nv_bfloat16* __restrict__ Bhg, const __nv_bfloat16* __restrict__ Blg,
    float* __restrict__ C, int M, int N, int K)
{
    extern __shared__ __align__(16) char dynsm[];
    gemm_bf16_body(Ahg, Alg, Bhg, Blg, C, M, N, K, blockIdx.x, blockIdx.y, dynsm);
}

// ---------------------------------------------------------------------------
// Hybrid top-k: radix threshold on fast scores, margin band, exact chunked-
// fp32 rescore, PARALLEL rank-based selection (no serial thread-0 loop).
// ---------------------------------------------------------------------------
__device__ __forceinline__ unsigned int key_map(float f) {
    unsigned int u = __float_as_uint(f);
    return (u & 0x80000000u) ? ~u : (u | 0x80000000u);
}
__device__ __forceinline__ float key_unmap(unsigned int k) {
    unsigned int u = (k & 0x80000000u) ? (k ^ 0x80000000u) : ~k;
    return __uint_as_float(u);
}

#define CAND_CAP 256

__global__ void __launch_bounds__(256) topk_hybrid(
    const float* __restrict__ sc_fast, const float* __restrict__ h,
    const float* __restrict__ Wr2, const float* __restrict__ z,
    __nv_bfloat16* __restrict__ zh, __nv_bfloat16* __restrict__ zl)
{
    __shared__ unsigned int keys[DFF];
    __shared__ unsigned int hist[256];
    __shared__ unsigned char mask[DFF];
    __shared__ int s_nhi, s_ncand;
    __shared__ int s_cidx[CAND_CAP];
    __shared__ float s_cex[CAND_CAP];

    const int row = blockIdx.x;
    const int tid = threadIdx.x;
    const int wid = tid >> 5;
    const int lid = tid & 31;
    const float* srow = sc_fast + (size_t)row * DFF;
    const float* zrow = z + (size_t)row * DFF;
    const float* hrow = h + (size_t)row * DMODEL;

    if (tid == 0) { s_nhi = 0; s_ncand = 0; }
    for (int j = tid; j < DFF; j += 256)
        keys[j] = key_map(srow[j]);

    // radix select: 512th-largest fast key
    unsigned int prefix = 0, pmask = 0;
    int remaining = TOPK;
    #pragma unroll
    for (int p = 0; p < 4; p++) {
        const int shift = 24 - 8 * p;
        __syncthreads();
        if (tid < 256) hist[tid] = 0;
        __syncthreads();
        for (int j = tid; j < DFF; j += 256) {
            unsigned int k = keys[j];
            if ((k & pmask) == prefix)
                atomicAdd(&hist[(k >> shift) & 255u], 1u);
        }
        __syncthreads();
        int cum = 0, digit = 0;
        for (int bbin = 255; bbin >= 0; bbin--) {
            int c = (int)hist[bbin];
            if (cum + c >= remaining) { digit = bbin; break; }
            cum += c;
        }
        remaining -= cum;
        prefix |= ((unsigned int)digit) << shift;
        pmask  |= 0xFFu << shift;
    }
    const float Tf = key_unmap(prefix);
    const float M = fmaxf(4e-3f, 1e-3f * fabsf(Tf));   // 2-term bf16 max err ~1.5e-3
    const unsigned int hiK = key_map(Tf + M);
    const unsigned int loK = key_map(Tf - M);

    __syncthreads();
    for (int j = tid; j < DFF; j += 256) {
        unsigned int k = keys[j];
        if (k > hiK) {
            mask[j] = 1;
            atomicAdd(&s_nhi, 1);
        } else {
            mask[j] = 0;
            if (k >= loK) {
                int pos = atomicAdd(&s_ncand, 1);
                if (pos < CAND_CAP) s_cidx[pos] = j;
            }
        }
    }
    __syncthreads();

    const int ncand = min(s_ncand, CAND_CAP);
    const int slots = TOPK - s_nhi;
    // exact rescore (bit-identical chunked fp32): lane l = chunk l
    for (int c = wid; c < ncand; c += 8) {
        const int j = s_cidx[c];
        const float* wrow = Wr2 + (size_t)j * DMODEL;
        const int kb = lid * 32;
        float chk = 0.0f;
        #pragma unroll 8
        for (int k = 0; k < 32; k++)
            chk = fmaf(hrow[kb + k], wrow[kb + k], chk);
        float acc = 0.0f;
        #pragma unroll
        for (int l = 0; l < 32; l++) {
            float v = __shfl_sync(0xffffffffu, chk, l);
            acc = __fadd_rn(acc, v);
        }
        if (lid == 0) s_cex[c] = acc;
    }
    __syncthreads();

    // parallel rank selection: candidate wins a slot iff fewer than `slots`
    // candidates are strictly better by (exact desc, idx asc).
    for (int c = tid; c < ncand; c += 256) {
        const float  my_s = s_cex[c];
        const int    my_i = s_cidx[c];
        int rank = 0;
        for (int c2 = 0; c2 < ncand; c2++) {
            const float o_s = s_cex[c2];
            if (o_s > my_s || (o_s == my_s && s_cidx[c2] < my_i)) rank++;
        }
        if (rank < slots) mask[my_i] = 1;
    }
    __syncthreads();

    for (int j = tid * 2; j < DFF; j += 512) {
        float v0 = mask[j]     ? gelu_f(zrow[j])     : 0.0f;
        float v1 = mask[j + 1] ? gelu_f(zrow[j + 1]) : 0.0f;
        unsigned int H, L;
        split2(v0, v1, H, L);
        *(unsigned int*)(zh + (size_t)row * DFF + j) = H;
        *(unsigned int*)(zl + (size_t)row * DFF + j) = L;
    }
}

// ---------------------------------------------------------------------------
// Launch
// Inputs: 0:x 1:W1 2:W2 3:W_router_1 4:W_router_2 5:ln_gamma 6:ln_beta 7:top_k
// ---------------------------------------------------------------------------
extern "C" void kernel_launch(void* const* d_in, const int* in_sizes, int n_in,
                              void* d_out, int out_size)
{
    const float* x    = (const float*)d_in[0];
    const float* W1   = (const float*)d_in[1];
    const float* W2   = (const float*)d_in[2];
    const float* Wr1  = (const float*)d_in[3];
    const float* Wr2  = (const float*)d_in[4];
    const float* gma  = (const float*)d_in[5];
    const float* bta  = (const float*)d_in[6];
    float* out = (float*)d_out;

    float *xn, *h, *sc, *z;
    __nv_bfloat16 *xh, *xl, *hh, *hl, *w1h, *w1l, *w2h, *w2l, *wr2h, *zh, *zl;
    cudaGetSymbolAddress((void**)&xn, g_xn);
    cudaGetSymbolAddress((void**)&h,  g_h);
    cudaGetSymbolAddress((void**)&sc, g_sc);
    cudaGetSymbolAddress((void**)&z,  g_z);
    cudaGetSymbolAddress((void**)&xh, g_xh);
    cudaGetSymbolAddress((void**)&xl, g_xl);
    cudaGetSymbolAddress((void**)&hh, g_hh);
    cudaGetSymbolAddress((void**)&hl, g_hl);
    cudaGetSymbolAddress((void**)&w1h, g_w1h);
    cudaGetSymbolAddress((void**)&w1l, g_w1l);
    cudaGetSymbolAddress((void**)&w2h, g_w2h);
    cudaGetSymbolAddress((void**)&w2l, g_w2l);
    cudaGetSymbolAddress((void**)&wr2h, g_wr2h);
    cudaGetSymbolAddress((void**)&zh, g_zh);
    cudaGetSymbolAddress((void**)&zl, g_zl);

    cudaFuncSetAttribute(fused_h_z, cudaFuncAttributeMaxDynamicSharedMemorySize, TC_DYNSMEM);
    cudaFuncSetAttribute(gemm_bt_bf16v2, cudaFuncAttributeMaxDynamicSharedMemorySize, TC_DYNSMEM);
    cudaFuncSetAttribute(gemm_scores_2t, cudaFuncAttributeMaxDynamicSharedMemorySize, TC_DYNSMEM);

    // 1) xn = LN(x)
    ln_kernel<<<NROWS, 256>>>(x, gma, bta, xn);

    // 1b) bf16 splits: x/W1/W2 hi+lo; Wr2 hi only
    split_bf16_kernel<<<2048, 256>>>(x,   xh,   xl,   (size_t)NROWS * DMODEL / 4);
    split_bf16_kernel<<<1024, 256>>>(W1,  w1h,  w1l,  (size_t)DFF * DMODEL / 4);
    split_bf16_kernel<<<1024, 256>>>(W2,  w2h,  w2l,  (size_t)DMODEL * DFF / 4);
    split_bf16_hi_kernel<<<1024, 256>>>(Wr2, wr2h, (size_t)DFF * DMODEL / 4);

    // 2) fused: h = gelu(xn@Wr1^T) fp32 (fma pipe) ∥ z = x@W1^T bf16 3-term (tensor)
    fused_h_z<<<10240, 256, TC_DYNSMEM>>>(xn, Wr1, h, hh, hl, xh, xl, w1h, w1l, z);

    // 3) fast scores = (hh+hl) @ wr2h^T — standalone 2-term kernel
    gemm_scores_2t<<<dim3(DFF / 64, NROWS / 128), 256, TC_DYNSMEM>>>(
        hh, hl, wr2h, sc, NROWS, DFF, DMODEL);

    // 4) hybrid top-512: widened margin + exact rescore + parallel selection
    topk_hybrid<<<NROWS, 256>>>(sc, h, Wr2, z, zh, zl);

    // 5) out = z @ W2^T (bf16 3-term, proven path)
    gemm_bt_bf16v2<<<dim3(DMODEL / 64, NROWS / 128), 256, TC_DYNSMEM>>>(
        zh, zl, w2h, w2l, out, NROWS, DMODEL, DFF);
}

// round 13
// speedup vs baseline: 1.4178x; 1.4178x over previous
#include <cuda_runtime.h>
#include <cuda_bf16.h>
#include <stdint.h>
#include <cstdint>
#include <math.h>

#define NROWS 16384
#define DMODEL 1024
#define DFF 4096
#define TOPK 512

// Scratch (device globals)
__device__ float g_xn[(size_t)NROWS * DMODEL];
__device__ float g_h [(size_t)NROWS * DMODEL];
__device__ float g_sc[(size_t)NROWS * DFF];
__device__ float g_z [(size_t)NROWS * DFF];
__device__ __nv_bfloat16 g_xh [(size_t)NROWS * DMODEL];
__device__ __nv_bfloat16 g_xl [(size_t)NROWS * DMODEL];
__device__ __nv_bfloat16 g_hh [(size_t)NROWS * DMODEL];
__device__ __nv_bfloat16 g_hl [(size_t)NROWS * DMODEL];
__device__ __nv_bfloat16 g_w1h[(size_t)DFF * DMODEL];
__device__ __nv_bfloat16 g_w1l[(size_t)DFF * DMODEL];
__device__ __nv_bfloat16 g_w2h[(size_t)DMODEL * DFF];
__device__ __nv_bfloat16 g_w2l[(size_t)DMODEL * DFF];
__device__ __nv_bfloat16 g_wr2h[(size_t)DFF * DMODEL];
__device__ __nv_bfloat16 g_zh [(size_t)NROWS * DFF];
__device__ __nv_bfloat16 g_zl [(size_t)NROWS * DFF];

// ---------------------------------------------------------------------------
// XLA f32 erf polynomial, uncontracted
// ---------------------------------------------------------------------------
__device__ __forceinline__ float erf_xla(float xin) {
    float x = fminf(fmaxf(xin, -4.0f), 4.0f);
    float x2 = __fmul_rn(x, x);
    float p = -2.72614225801306e-10f;
    p = __fadd_rn(__fmul_rn(p, x2),  2.77068142495902e-08f);
    p = __fadd_rn(__fmul_rn(p, x2), -2.10102402082508e-06f);
    p = __fadd_rn(__fmul_rn(p, x2), -5.69250639462346e-05f);
    p = __fadd_rn(__fmul_rn(p, x2), -7.34990630326855e-04f);
    p = __fadd_rn(__fmul_rn(p, x2), -2.95459980854025e-03f);
    p = __fadd_rn(__fmul_rn(p, x2), -1.60960333262415e-02f);
    float q = -1.45660718464996e-05f;
    q = __fadd_rn(__fmul_rn(q, x2), -2.13374055278905e-04f);
    q = __fadd_rn(__fmul_rn(q, x2), -1.68282697438203e-03f);
    q = __fadd_rn(__fmul_rn(q, x2), -7.37332916720468e-03f);
    q = __fadd_rn(__fmul_rn(q, x2), -1.42647390514189e-02f);
    return __fdiv_rn(__fmul_rn(x, p), q);
}

__device__ __forceinline__ float gelu_f(float v) {
    float t = __fdiv_rn(v, 1.41421356237309504880f);
    float e = erf_xla(t);
    return __fmul_rn(__fmul_rn(v, __fadd_rn(e, 1.0f)), 0.5f);
}

// ---------------------------------------------------------------------------
// LayerNorm (unchanged, passing)
// ---------------------------------------------------------------------------
__global__ void __launch_bounds__(256) ln_kernel(
    const float* __restrict__ x, const float* __restrict__ g,
    const float* __restrict__ b, float* __restrict__ o)
{
    __shared__ double red[8];
    __shared__ float s_mu, s_inv;
    const int row = blockIdx.x;
    const int tid = threadIdx.x;
    const float4* xr = (const float4*)(x + (size_t)row * DMODEL);
    float4* orow = (float4*)(o + (size_t)row * DMODEL);

    float4 v = xr[tid];

    double s = (double)v.x + (double)v.y + (double)v.z + (double)v.w;
    #pragma unroll
    for (int off = 16; off; off >>= 1) s += __shfl_down_sync(0xffffffffu, s, off);
    if ((tid & 31) == 0) red[tid >> 5] = s;
    __syncthreads();
    if (tid == 0) {
        double S = 0.0;
        #pragma unroll
        for (int w = 0; w < 8; w++) S += red[w];
        s_mu = (float)(S * (1.0 / DMODEL));
    }
    __syncthreads();
    const float mu = s_mu;
    __syncthreads();

    float dx0 = __fsub_rn(v.x, mu), dx1 = __fsub_rn(v.y, mu);
    float dx2 = __fsub_rn(v.z, mu), dx3 = __fsub_rn(v.w, mu);
    double ss = (double)__fmul_rn(dx0, dx0) + (double)__fmul_rn(dx1, dx1)
              + (double)__fmul_rn(dx2, dx2) + (double)__fmul_rn(dx3, dx3);
    #pragma unroll
    for (int off = 16; off; off >>= 1) ss += __shfl_down_sync(0xffffffffu, ss, off);
    if ((tid & 31) == 0) red[tid >> 5] = ss;
    __syncthreads();
    if (tid == 0) {
        double SS = 0.0;
        #pragma unroll
        for (int w = 0; w < 8; w++) SS += red[w];
        float var = (float)(SS * (1.0 / DMODEL));
        s_inv = (float)(1.0 / sqrt((double)__fadd_rn(var, 1e-5f)));
    }
    __syncthreads();
    const float inv = s_inv;
    const float4 gv = ((const float4*)g)[tid];
    const float4 bv = ((const float4*)b)[tid];
    float4 r;
    r.x = __fadd_rn(__fmul_rn(__fmul_rn(dx0, inv), gv.x), bv.x);
    r.y = __fadd_rn(__fmul_rn(__fmul_rn(dx1, inv), gv.y), bv.y);
    r.z = __fadd_rn(__fmul_rn(__fmul_rn(dx2, inv), gv.z), bv.z);
    r.w = __fadd_rn(__fmul_rn(__fmul_rn(dx3, inv), gv.w), bv.w);
    orow[tid] = r;
}

// ---------------------------------------------------------------------------
// fp32 -> bf16 hi/lo split
// ---------------------------------------------------------------------------
union bfu { __nv_bfloat162 b; unsigned int u; };

__device__ __forceinline__ void split2(float a, float b, unsigned int& hi, unsigned int& lo) {
    __nv_bfloat16 h0 = __float2bfloat16_rn(a);
    __nv_bfloat16 h1 = __float2bfloat16_rn(b);
    __nv_bfloat16 l0 = __float2bfloat16_rn(__fsub_rn(a, __bfloat162float(h0)));
    __nv_bfloat16 l1 = __float2bfloat16_rn(__fsub_rn(b, __bfloat162float(h1)));
    bfu H; H.b = __nv_bfloat162(h0, h1); hi = H.u;
    bfu L; L.b = __nv_bfloat162(l0, l1); lo = L.u;
}

__global__ void __launch_bounds__(256) split_bf16_kernel(
    const float* __restrict__ src, __nv_bfloat16* __restrict__ hi,
    __nv_bfloat16* __restrict__ lo, size_t n4)
{
    size_t i = (size_t)blockIdx.x * 256 + threadIdx.x;
    size_t stride = (size_t)gridDim.x * 256;
    for (; i < n4; i += stride) {
        float4 v = ((const float4*)src)[i];
        uint2 H, L;
        split2(v.x, v.y, H.x, L.x);
        split2(v.z, v.w, H.y, L.y);
        ((uint2*)hi)[i] = H;
        ((uint2*)lo)[i] = L;
    }
}

// hi-only split (Wr2: 2-term scores need no B-lo)
__global__ void __launch_bounds__(256) split_bf16_hi_kernel(
    const float* __restrict__ src, __nv_bfloat16* __restrict__ hi, size_t n4)
{
    size_t i = (size_t)blockIdx.x * 256 + threadIdx.x;
    size_t stride = (size_t)gridDim.x * 256;
    for (; i < n4; i += stride) {
        float4 v = ((const float4*)src)[i];
        bfu a, b;
        a.b = __nv_bfloat162(__float2bfloat16_rn(v.x), __float2bfloat16_rn(v.y));
        b.b = __nv_bfloat162(__float2bfloat16_rn(v.z), __float2bfloat16_rn(v.w));
        uint2 H; H.x = a.u; H.y = b.u;
        ((uint2*)hi)[i] = H;
    }
}

// ---------------------------------------------------------------------------
// mma / ldmatrix / cp.async primitives
// ---------------------------------------------------------------------------
__device__ __forceinline__ void mma16_bf16(float c[4], const unsigned int a[4],
                                           const unsigned int b[2]) {
    asm volatile("mma.sync.aligned.m16n8k16.row.col.f32.bf16.bf16.f32 "
        "{%0,%1,%2,%3}, {%4,%5,%6,%7}, {%8,%9}, {%0,%1,%2,%3};\n"
        : "+f"(c[0]), "+f"(c[1]), "+f"(c[2]), "+f"(c[3])
        : "r"(a[0]), "r"(a[1]), "r"(a[2]), "r"(a[3]), "r"(b[0]), "r"(b[1]));
}
__device__ __forceinline__ void ldsm4(unsigned int& r0, unsigned int& r1,
                                      unsigned int& r2, unsigned int& r3,
                                      const void* p) {
    unsigned int a = (unsigned int)__cvta_generic_to_shared(p);
    asm volatile("ldmatrix.sync.aligned.m8n8.x4.shared.b16 {%0,%1,%2,%3}, [%4];"
                 : "=r"(r0), "=r"(r1), "=r"(r2), "=r"(r3) : "r"(a));
}
__device__ __forceinline__ void cpa16(void* s, const void* g) {
    unsigned int a = (unsigned int)__cvta_generic_to_shared(s);
    asm volatile("cp.async.cg.shared.global [%0], [%1], 16;\n"
                 :: "r"(a), "l"(g) : "memory");
}
__device__ __forceinline__ void cpa_commit() {
    asm volatile("cp.async.commit_group;\n" ::: "memory");
}
template <int N>
__device__ __forceinline__ void cpa_wait() {
    asm volatile("cp.async.wait_group %0;\n" :: "n"(N) : "memory");
}

// ---------------------------------------------------------------------------
// bf16 3-term GEMM body (ldmatrix + cp.async, 3-stage) — UNCHANGED, passing.
// ---------------------------------------------------------------------------
#define STG_STRIDE 18432
#define TC_DYNSMEM (3 * STG_STRIDE)

__device__ __forceinline__ void issue_chunk(
    char* sm, int st, int k0,
    const __nv_bfloat16* Ag0, const __nv_bfloat16* Ag1, const __nv_bfloat16* Bg,
    int arow, int akb, int brow, int bkb, int boff)
{
    char* base = sm + st * STG_STRIDE;
    cpa16(base + arow * 48 + akb,        Ag0 + k0);
    cpa16(base + 6144 + arow * 48 + akb, Ag1 + k0);
    cpa16(base + boff + brow * 48 + bkb, Bg + k0);
    cpa_commit();
}

__device__ __forceinline__ void gemm_bf16_body(
    const __nv_bfloat16* __restrict__ Ahg, const __nv_bfloat16* __restrict__ Alg,
    const __nv_bfloat16* __restrict__ Bhg, const __nv_bfloat16* __restrict__ Blg,
    float* __restrict__ C, int M, int N, int K, int bx, int by, char* sm)
{
    const int tid  = threadIdx.x;
    const int m0   = by * 128;
    const int n0   = bx * 64;
    const int wid  = tid >> 5;
    const int lane = tid & 31;
    const int gid  = lane >> 2;
    const int tig  = lane & 3;
    const int wm   = (wid & 3) * 32;
    const int wn   = (wid >> 2) * 32;
    const int g8   = lane >> 3;
    const int r8   = lane & 7;

    const int arow = tid >> 1, akb = (tid & 1) * 16, ak = (tid & 1) * 8;
    const int bt = tid & 127;
    const int brow = bt >> 1, bkb = (bt & 1) * 16, bk = (bt & 1) * 8;
    const bool bhi = tid < 128;
    const int boff = bhi ? 12288 : 15360;

    const __nv_bfloat16* Ag0 = Ahg + (size_t)(m0 + arow) * K + ak;
    const __nv_bfloat16* Ag1 = Alg + (size_t)(m0 + arow) * K + ak;
    const __nv_bfloat16* Bg  = (bhi ? Bhg : Blg) + (size_t)(n0 + brow) * K + bk;

    float acc[2][4][4];
    #pragma unroll
    for (int mt = 0; mt < 2; mt++)
        #pragma unroll
        for (int nt = 0; nt < 4; nt++)
            #pragma unroll
            for (int r = 0; r < 4; r++) acc[mt][nt][r] = 0.0f;

    const int a_row = wm + (g8 & 1) * 8 + r8;
    const int a_col = (g8 >> 1) * 16;
    const int b_row = wn + (g8 >> 1) * 8 + r8;
    const int b_col = (g8 & 1) * 16;

    const int NC = K >> 4;
    issue_chunk(sm, 0, 0,  Ag0, Ag1, Bg, arow, akb, brow, bkb, boff);
    issue_chunk(sm, 1, 16, Ag0, Ag1, Bg, arow, akb, brow, bkb, boff);

    for (int i = 0; i < NC; i++) {
        const int st = i % 3;
        if (i + 2 < NC) cpa_wait<1>(); else cpa_wait<0>();
        __syncthreads();
        if (i + 2 < NC)
            issue_chunk(sm, (i + 2) % 3, (i + 2) * 16,
                        Ag0, Ag1, Bg, arow, akb, brow, bkb, boff);

        char* base = sm + st * STG_STRIDE;
        unsigned int afh[2][4], afl[2][4], bfh[4][2], bfl[4][2];
        #pragma unroll
        for (int mt = 0; mt < 2; mt++) {
            const int ro = (a_row + mt * 16) * 48 + a_col;
            ldsm4(afh[mt][0], afh[mt][1], afh[mt][2], afh[mt][3], base + ro);
            ldsm4(afl[mt][0], afl[mt][1], afl[mt][2], afl[mt][3], base + 6144 + ro);
        }
        #pragma unroll
        for (int p = 0; p < 2; p++) {
            const int ro = (b_row + p * 16) * 48 + b_col;
            ldsm4(bfh[p*2][0], bfh[p*2][1], bfh[p*2+1][0], bfh[p*2+1][1],
                  base + 12288 + ro);
            ldsm4(bfl[p*2][0], bfl[p*2][1], bfl[p*2+1][0], bfl[p*2+1][1],
                  base + 15360 + ro);
        }
        #pragma unroll
        for (int mt = 0; mt < 2; mt++)
            #pragma unroll
            for (int nt = 0; nt < 4; nt++) {
                mma16_bf16(acc[mt][nt], afh[mt], bfh[nt]);
                mma16_bf16(acc[mt][nt], afh[mt], bfl[nt]);
                mma16_bf16(acc[mt][nt], afl[mt], bfh[nt]);
            }
    }

    #pragma unroll
    for (int mt = 0; mt < 2; mt++)
        #pragma unroll
        for (int nt = 0; nt < 4; nt++) {
            const int r0 = m0 + wm + mt * 16 + gid;
            const int c0 = n0 + wn + nt * 8 + tig * 2;
            *(float2*)&C[(size_t)r0 * N + c0]       = make_float2(acc[mt][nt][0], acc[mt][nt][1]);
            *(float2*)&C[(size_t)(r0 + 8) * N + c0] = make_float2(acc[mt][nt][2], acc[mt][nt][3]);
        }
}

// ---------------------------------------------------------------------------
// STANDALONE 2-term scores GEMM: C = (Ah + Al) @ Bh^T (verbatim from R12,
// verified correct).
// ---------------------------------------------------------------------------
__global__ void __launch_bounds__(256) gemm_scores_2t(
    const __nv_bfloat16* __restrict__ Ahg, const __nv_bfloat16* __restrict__ Alg,
    const __nv_bfloat16* __restrict__ Bhg,
    float* __restrict__ C, int M, int N, int K)
{
    extern __shared__ __align__(16) char sm[];
    const int tid  = threadIdx.x;
    const int m0   = (int)blockIdx.y * 128;
    const int n0   = (int)blockIdx.x * 64;
    const int wid  = tid >> 5;
    const int lane = tid & 31;
    const int gid  = lane >> 2;
    const int tig  = lane & 3;
    const int wm   = (wid & 3) * 32;
    const int wn   = (wid >> 2) * 32;
    const int g8   = lane >> 3;
    const int r8   = lane & 7;

    const int arow = tid >> 1, akb = (tid & 1) * 16, ak = (tid & 1) * 8;
    const int bt = tid & 127;
    const int brow = bt >> 1, bkb = (bt & 1) * 16, bk = (bt & 1) * 8;
    const bool bact = tid < 128;

    const __nv_bfloat16* Ag0 = Ahg + (size_t)(m0 + arow) * K + ak;
    const __nv_bfloat16* Ag1 = Alg + (size_t)(m0 + arow) * K + ak;
    const __nv_bfloat16* Bg  = Bhg + (size_t)(n0 + brow) * K + bk;

    float acc[2][4][4];
    #pragma unroll
    for (int mt = 0; mt < 2; mt++)
        #pragma unroll
        for (int nt = 0; nt < 4; nt++)
            #pragma unroll
            for (int r = 0; r < 4; r++) acc[mt][nt][r] = 0.0f;

    const int a_row = wm + (g8 & 1) * 8 + r8;
    const int a_col = (g8 >> 1) * 16;
    const int b_row = wn + (g8 >> 1) * 8 + r8;
    const int b_col = (g8 & 1) * 16;

    const int NC = K >> 4;
    #pragma unroll
    for (int pr = 0; pr < 2; pr++) {
        char* base = sm + pr * STG_STRIDE;
        cpa16(base + arow * 48 + akb,        Ag0 + pr * 16);
        cpa16(base + 6144 + arow * 48 + akb, Ag1 + pr * 16);
        if (bact) cpa16(base + 12288 + brow * 48 + bkb, Bg + pr * 16);
        cpa_commit();
    }

    for (int i = 0; i < NC; i++) {
        const int st = i % 3;
        if (i + 2 < NC) cpa_wait<1>(); else cpa_wait<0>();
        __syncthreads();
        if (i + 2 < NC) {
            char* nb = sm + ((i + 2) % 3) * STG_STRIDE;
            const int k0 = (i + 2) * 16;
            cpa16(nb + arow * 48 + akb,        Ag0 + k0);
            cpa16(nb + 6144 + arow * 48 + akb, Ag1 + k0);
            if (bact) cpa16(nb + 12288 + brow * 48 + bkb, Bg + k0);
            cpa_commit();
        }

        char* base = sm + st * STG_STRIDE;
        unsigned int afh[2][4], afl[2][4], bfh[4][2];
        #pragma unroll
        for (int mt = 0; mt < 2; mt++) {
            const int ro = (a_row + mt * 16) * 48 + a_col;
            ldsm4(afh[mt][0], afh[mt][1], afh[mt][2], afh[mt][3], base + ro);
            ldsm4(afl[mt][0], afl[mt][1], afl[mt][2], afl[mt][3], base + 6144 + ro);
        }
        #pragma unroll
        for (int p = 0; p < 2; p++) {
            const int ro = (b_row + p * 16) * 48 + b_col;
            ldsm4(bfh[p*2][0], bfh[p*2][1], bfh[p*2+1][0], bfh[p*2+1][1],
                  base + 12288 + ro);
        }
        #pragma unroll
        for (int mt = 0; mt < 2; mt++)
            #pragma unroll
            for (int nt = 0; nt < 4; nt++) {
                mma16_bf16(acc[mt][nt], afh[mt], bfh[nt]);
                mma16_bf16(acc[mt][nt], afl[mt], bfh[nt]);
            }
    }

    #pragma unroll
    for (int mt = 0; mt < 2; mt++)
        #pragma unroll
        for (int nt = 0; nt < 4; nt++) {
            const int r0 = m0 + wm + mt * 16 + gid;
            const int c0 = n0 + wn + nt * 8 + tig * 2;
            *(float2*)&C[(size_t)r0 * N + c0]       = make_float2(acc[mt][nt][0], acc[mt][nt][1]);
            *(float2*)&C[(size_t)(r0 + 8) * N + c0] = make_float2(acc[mt][nt][2], acc[mt][nt][3]);
        }
}

// ---------------------------------------------------------------------------
// fp32 chunked GEMM body for h, with gelu + bf16-split epilogue (unchanged)
// ---------------------------------------------------------------------------
__device__ __forceinline__ void acc_body_h(
    const float* __restrict__ A, const float* __restrict__ B,
    float* __restrict__ C, __nv_bfloat16* __restrict__ Ch,
    __nv_bfloat16* __restrict__ Cl, int M, int N, int K, int bx, int by)
{
    __shared__ float As[8][128];
    __shared__ float Bs[8][64];

    const int m0 = by * 128;
    const int n0 = bx * 64;
    const int tid = threadIdx.x;
    const int lrA = tid >> 1;
    const int lcA = (tid & 1) * 4;
    const int lrB = tid >> 2;
    const int lcB = (tid & 3) * 2;
    const int tx = tid & 15;
    const int ty = tid >> 4;

    const float* Aptr = A + (size_t)(m0 + lrA) * K + lcA;
    const float* Bptr = B + (size_t)(n0 + lrB) * K + lcB;

    float acc[8][4], chk[8][4];
    #pragma unroll
    for (int i = 0; i < 8; i++)
        #pragma unroll
        for (int j = 0; j < 4; j++) { acc[i][j] = 0.0f; chk[i][j] = 0.0f; }

    float4 av = *(const float4*)(Aptr);
    float2 bv = *(const float2*)(Bptr);

    for (int k0 = 0; k0 < K; k0 += 8) {
        As[lcA + 0][lrA] = av.x; As[lcA + 1][lrA] = av.y;
        As[lcA + 2][lrA] = av.z; As[lcA + 3][lrA] = av.w;
        Bs[lcB + 0][lrB] = bv.x; Bs[lcB + 1][lrB] = bv.y;
        __syncthreads();

        if (k0 + 8 < K) {
            av = *(const float4*)(Aptr + k0 + 8);
            bv = *(const float2*)(Bptr + k0 + 8);
        }

        #pragma unroll
        for (int kk = 0; kk < 8; kk++) {
            float4 a0 = *(const float4*)&As[kk][ty * 4];
            float4 a1 = *(const float4*)&As[kk][64 + ty * 4];
            float4 b0 = *(const float4*)&Bs[kk][tx * 4];
            float ar[8] = {a0.x, a0.y, a0.z, a0.w, a1.x, a1.y, a1.z, a1.w};
            float br[4] = {b0.x, b0.y, b0.z, b0.w};
            #pragma unroll
            for (int i = 0; i < 8; i++)
                #pragma unroll
                for (int j = 0; j < 4; j++)
                    chk[i][j] = fmaf(ar[i], br[j], chk[i][j]);
        }
        if ((k0 & 24) == 24) {
            #pragma unroll
            for (int i = 0; i < 8; i++)
                #pragma unroll
                for (int j = 0; j < 4; j++) {
                    acc[i][j] = __fadd_rn(acc[i][j], chk[i][j]);
                    chk[i][j] = 0.0f;
                }
        }
        __syncthreads();
    }

    #pragma unroll
    for (int i = 0; i < 8; i++) {
        const int row = m0 + ((i < 4) ? (ty * 4 + i) : (64 + ty * 4 + i - 4));
        float v0 = gelu_f(acc[i][0]), v1 = gelu_f(acc[i][1]);
        float v2 = gelu_f(acc[i][2]), v3 = gelu_f(acc[i][3]);
        float4 r; r.x = v0; r.y = v1; r.z = v2; r.w = v3;
        *(float4*)(C + (size_t)row * N + n0 + tx * 4) = r;
        unsigned int H0, L0, H1, L1;
        split2(v0, v1, H0, L0);
        split2(v2, v3, H1, L1);
        uint2 H; H.x = H0; H.y = H1;
        uint2 L; L.x = L0; L.y = L1;
        *(uint2*)(Ch + (size_t)row * N + n0 + tx * 4) = H;
        *(uint2*)(Cl + (size_t)row * N + n0 + tx * 4) = L;
    }
}

// ---------------------------------------------------------------------------
// Fused heterogeneous kernel: 1/5 h (fma pipe), 4/5 z (tensor pipe)
// ---------------------------------------------------------------------------
__global__ void __launch_bounds__(256) fused_h_z(
    const float* __restrict__ xn, const float* __restrict__ Wr1,
    float* __restrict__ h, __nv_bfloat16* __restrict__ hh, __nv_bfloat16* __restrict__ hl,
    const __nv_bfloat16* __restrict__ xh, const __nv_bfloat16* __restrict__ xl,
    const __nv_bfloat16* __restrict__ w1h, const __nv_bfloat16* __restrict__ w1l,
    float* __restrict__ z)
{
    extern __shared__ __align__(16) char dynsm[];
    const int bid = blockIdx.x;
    if (bid % 5 == 0) {
        const int sid = bid / 5;
        acc_body_h(xn, Wr1, h, hh, hl, NROWS, DMODEL, DMODEL, sid & 15, sid >> 4);
    } else {
        const int sid = bid - bid / 5 - 1;
        gemm_bf16_body(xh, xl, w1h, w1l, z, NROWS, DFF, DMODEL, sid & 63, sid >> 6, dynsm);
    }
}

__global__ void __launch_bounds__(256) gemm_bt_bf16v2(
    const __nv_bfloat16* __restrict__ Ahg, const __nv_bfloat16* __restrict__ Alg,
    const __nv_bfloat16* __restrict__ Bhg, const __nv_bfloat16* __restrict__ Blg,
    float* __restrict__ C, int M, int N, int K)
{
    extern __shared__ __align__(16) char dynsm[];
    gemm_bf16_body(Ahg, Alg, Bhg, Blg, C, M, N, K, blockIdx.x, blockIdx.y, dynsm);
}

// ---------------------------------------------------------------------------
// Hybrid top-k: radix threshold on fast scores, margin band, COALESCED
// smem-staged exact rescore (bit-identical chunked fp32 math), parallel
// rank selection, then split(mask*gelu(z)).
// ---------------------------------------------------------------------------
__device__ __forceinline__ unsigned int key_map(float f) {
    unsigned int u = __float_as_uint(f);
    return (u & 0x80000000u) ? ~u : (u | 0x80000000u);
}
__device__ __forceinline__ float key_unmap(unsigned int k) {
    unsigned int u = (k & 0x80000000u) ? (k ^ 0x80000000u) : ~k;
    return __uint_as_float(u);
}

#define CAND_CAP 256

__global__ void __launch_bounds__(256) topk_hybrid(
    const float* __restrict__ sc_fast, const float* __restrict__ h,
    const float* __restrict__ Wr2, const float* __restrict__ z,
    __nv_bfloat16* __restrict__ zh, __nv_bfloat16* __restrict__ zl)
{
    __shared__ unsigned int keys[DFF];          // reused as ws staging in rescore
    __shared__ unsigned int hist[256];
    __shared__ unsigned char mask[DFF];
    __shared__ int s_nhi, s_ncand;
    __shared__ int s_cidx[CAND_CAP];
    __shared__ float s_cex[CAND_CAP];
    __shared__ float hs[32 * 33];               // staged h row, padded pitch 33
    __shared__ float chks[2][32];

    const int row = blockIdx.x;
    const int tid = threadIdx.x;
    const int wid = tid >> 5;
    const int lid = tid & 31;
    const float* srow = sc_fast + (size_t)row * DFF;
    const float* zrow = z + (size_t)row * DFF;
    const float* hrow = h + (size_t)row * DMODEL;

    if (tid == 0) { s_nhi = 0; s_ncand = 0; }
    for (int j = tid; j < DFF; j += 256)
        keys[j] = key_map(srow[j]);

    // radix select: 512th-largest fast key
    unsigned int prefix = 0, pmask = 0;
    int remaining = TOPK;
    #pragma unroll
    for (int p = 0; p < 4; p++) {
        const int shift = 24 - 8 * p;
        __syncthreads();
        if (tid < 256) hist[tid] = 0;
        __syncthreads();
        for (int j = tid; j < DFF; j += 256) {
            unsigned int k = keys[j];
            if ((k & pmask) == prefix)
                atomicAdd(&hist[(k >> shift) & 255u], 1u);
        }
        __syncthreads();
        int cum = 0, digit = 0;
        for (int bbin = 255; bbin >= 0; bbin--) {
            int c = (int)hist[bbin];
            if (cum + c >= remaining) { digit = bbin; break; }
            cum += c;
        }
        remaining -= cum;
        prefix |= ((unsigned int)digit) << shift;
        pmask  |= 0xFFu << shift;
    }
    const float Tf = key_unmap(prefix);
    // 2-term fast-score max error ~1.7e-3; need M >= 2*maxerr
    const float M = fmaxf(4e-3f, 1e-3f * fabsf(Tf));
    const unsigned int hiK = key_map(Tf + M);
    const unsigned int loK = key_map(Tf - M);

    __syncthreads();
    for (int j = tid; j < DFF; j += 256) {
        unsigned int k = keys[j];
        if (k > hiK) {
            mask[j] = 1;
            atomicAdd(&s_nhi, 1);
        } else {
            mask[j] = 0;
            if (k >= loK) {
                int pos = atomicAdd(&s_ncand, 1);
                if (pos < CAND_CAP) s_cidx[pos] = j;
            }
        }
    }
    __syncthreads();

    const int ncand = min(s_ncand, CAND_CAP);
    const int slots = TOPK - s_nhi;

    // stage h row once (coalesced, padded): hs[c*33+p] = h[c*32+p]
    for (int i = tid; i < DMODEL; i += 256)
        hs[(i >> 5) * 33 + (i & 31)] = hrow[i];
    float* ws = (float*)keys;   // 4096 floats: two 1056-float staging slots
    __syncthreads();            // keys reads done; h staged

    // exact rescore, 2 candidates per iteration, coalesced Wr2 loads.
    // Math bit-identical to chunked fp32: lane l = chunk l (32 sequential
    // fmaf), then in-order fold of the 32 chunk sums.
    for (int c0 = 0; c0 < ncand; c0 += 2) {
        const int nc = min(2, ncand - c0);
        for (int q = 0; q < nc; q++) {
            const float* wrow = Wr2 + (size_t)s_cidx[c0 + q] * DMODEL;
            for (int i = tid; i < DMODEL; i += 256)
                ws[q * 2048 + (i >> 5) * 33 + (i & 31)] = wrow[i];
        }
        __syncthreads();
        if (wid < nc) {
            const float* wp = ws + wid * 2048;
            const int b = lid * 33;
            float chk = 0.0f;
            #pragma unroll
            for (int k = 0; k < 32; k++)
                chk = fmaf(hs[b + k], wp[b + k], chk);
            chks[wid][lid] = chk;
            __syncwarp();
            if (lid == 0) {
                float a = 0.0f;
                #pragma unroll
                for (int l = 0; l < 32; l++)
                    a = __fadd_rn(a, chks[wid][l]);
                s_cex[c0 + wid] = a;
            }
        }
        __syncthreads();
    }

    // parallel rank selection: candidate wins a slot iff fewer than `slots`
    // candidates are strictly better by (exact desc, idx asc).
    for (int c = tid; c < ncand; c += 256) {
        const float my_s = s_cex[c];
        const int   my_i = s_cidx[c];
        int rank = 0;
        for (int c2 = 0; c2 < ncand; c2++) {
            const float o_s = s_cex[c2];
            if (o_s > my_s || (o_s == my_s && s_cidx[c2] < my_i)) rank++;
        }
        if (rank < slots) mask[my_i] = 1;
    }
    __syncthreads();

    for (int j = tid * 2; j < DFF; j += 512) {
        float v0 = mask[j]     ? gelu_f(zrow[j])     : 0.0f;
        float v1 = mask[j + 1] ? gelu_f(zrow[j + 1]) : 0.0f;
        unsigned int H, L;
        split2(v0, v1, H, L);
        *(unsigned int*)(zh + (size_t)row * DFF + j) = H;
        *(unsigned int*)(zl + (size_t)row * DFF + j) = L;
    }
}

// ---------------------------------------------------------------------------
// Launch
// Inputs: 0:x 1:W1 2:W2 3:W_router_1 4:W_router_2 5:ln_gamma 6:ln_beta 7:top_k
// ---------------------------------------------------------------------------
extern "C" void kernel_launch(void* const* d_in, const int* in_sizes, int n_in,
                              void* d_out, int out_size)
{
    const float* x    = (const float*)d_in[0];
    const float* W1   = (const float*)d_in[1];
    const float* W2   = (const float*)d_in[2];
    const float* Wr1  = (const float*)d_in[3];
    const float* Wr2  = (const float*)d_in[4];
    const float* gma  = (const float*)d_in[5];
    const float* bta  = (const float*)d_in[6];
    float* out = (float*)d_out;

    float *xn, *h, *sc, *z;
    __nv_bfloat16 *xh, *xl, *hh, *hl, *w1h, *w1l, *w2h, *w2l, *wr2h, *zh, *zl;
    cudaGetSymbolAddress((void**)&xn, g_xn);
    cudaGetSymbolAddress((void**)&h,  g_h);
    cudaGetSymbolAddress((void**)&sc, g_sc);
    cudaGetSymbolAddress((void**)&z,  g_z);
    cudaGetSymbolAddress((void**)&xh, g_xh);
    cudaGetSymbolAddress((void**)&xl, g_xl);
    cudaGetSymbolAddress((void**)&hh, g_hh);
    cudaGetSymbolAddress((void**)&hl, g_hl);
    cudaGetSymbolAddress((void**)&w1h, g_w1h);
    cudaGetSymbolAddress((void**)&w1l, g_w1l);
    cudaGetSymbolAddress((void**)&w2h, g_w2h);
    cudaGetSymbolAddress((void**)&w2l, g_w2l);
    cudaGetSymbolAddress((void**)&wr2h, g_wr2h);
    cudaGetSymbolAddress((void**)&zh, g_zh);
    cudaGetSymbolAddress((void**)&zl, g_zl);

    cudaFuncSetAttribute(fused_h_z, cudaFuncAttributeMaxDynamicSharedMemorySize, TC_DYNSMEM);
    cudaFuncSetAttribute(gemm_bt_bf16v2, cudaFuncAttributeMaxDynamicSharedMemorySize, TC_DYNSMEM);
    cudaFuncSetAttribute(gemm_scores_2t, cudaFuncAttributeMaxDynamicSharedMemorySize, TC_DYNSMEM);

    // 1) xn = LN(x)
    ln_kernel<<<NROWS, 256>>>(x, gma, bta, xn);

    // 1b) bf16 splits: x/W1/W2 hi+lo; Wr2 hi only
    split_bf16_kernel<<<2048, 256>>>(x,   xh,   xl,   (size_t)NROWS * DMODEL / 4);
    split_bf16_kernel<<<1024, 256>>>(W1,  w1h,  w1l,  (size_t)DFF * DMODEL / 4);
    split_bf16_kernel<<<1024, 256>>>(W2,  w2h,  w2l,  (size_t)DMODEL * DFF / 4);
    split_bf16_hi_kernel<<<1024, 256>>>(Wr2, wr2h, (size_t)DFF * DMODEL / 4);

    // 2) fused: h = gelu(xn@Wr1^T) fp32 (fma pipe) ∥ z = x@W1^T bf16 3-term (tensor)
    fused_h_z<<<10240, 256, TC_DYNSMEM>>>(xn, Wr1, h, hh, hl, xh, xl, w1h, w1l, z);

    // 3) fast scores = (hh+hl) @ wr2h^T — standalone 2-term kernel
    gemm_scores_2t<<<dim3(DFF / 64, NROWS / 128), 256, TC_DYNSMEM>>>(
        hh, hl, wr2h, sc, NROWS, DFF, DMODEL);

    // 4) hybrid top-512: margin band + coalesced exact rescore + parallel rank
    topk_hybrid<<<NROWS, 256>>>(sc, h, Wr2, z, zh, zl);

    // 5) out = z @ W2^T (bf16 3-term, proven path)
    gemm_bt_bf16v2<<<dim3(DMODEL / 64, NROWS / 128), 256, TC_DYNSMEM>>>(
        zh, zl, w2h, w2l, out, NROWS, DMODEL, DFF);
}

// round 14
// speedup vs baseline: 1.4401x; 1.0158x over previous
#include <cuda_runtime.h>
#include <cuda_bf16.h>
#include <stdint.h>
#include <cstdint>
#include <math.h>

#define NROWS 16384
#define DMODEL 1024
#define DFF 4096
#define TOPK 512

// Scratch (device globals)
__device__ float g_xn[(size_t)NROWS * DMODEL];
__device__ float g_h [(size_t)NROWS * DMODEL];
__device__ float g_sc[(size_t)NROWS * DFF];
__device__ float g_z [(size_t)NROWS * DFF];
__device__ __nv_bfloat16 g_xh [(size_t)NROWS * DMODEL];
__device__ __nv_bfloat16 g_xl [(size_t)NROWS * DMODEL];
__device__ __nv_bfloat16 g_hh [(size_t)NROWS * DMODEL];
__device__ __nv_bfloat16 g_hl [(size_t)NROWS * DMODEL];
__device__ __nv_bfloat16 g_w1h[(size_t)DFF * DMODEL];
__device__ __nv_bfloat16 g_w1l[(size_t)DFF * DMODEL];
__device__ __nv_bfloat16 g_w2h[(size_t)DMODEL * DFF];
__device__ __nv_bfloat16 g_w2l[(size_t)DMODEL * DFF];
__device__ __nv_bfloat16 g_wr2h[(size_t)DFF * DMODEL];
__device__ __nv_bfloat16 g_zh [(size_t)NROWS * DFF];
__device__ __nv_bfloat16 g_zl [(size_t)NROWS * DFF];

// ---------------------------------------------------------------------------
// XLA f32 erf polynomial, uncontracted
// ---------------------------------------------------------------------------
__device__ __forceinline__ float erf_xla(float xin) {
    float x = fminf(fmaxf(xin, -4.0f), 4.0f);
    float x2 = __fmul_rn(x, x);
    float p = -2.72614225801306e-10f;
    p = __fadd_rn(__fmul_rn(p, x2),  2.77068142495902e-08f);
    p = __fadd_rn(__fmul_rn(p, x2), -2.10102402082508e-06f);
    p = __fadd_rn(__fmul_rn(p, x2), -5.69250639462346e-05f);
    p = __fadd_rn(__fmul_rn(p, x2), -7.34990630326855e-04f);
    p = __fadd_rn(__fmul_rn(p, x2), -2.95459980854025e-03f);
    p = __fadd_rn(__fmul_rn(p, x2), -1.60960333262415e-02f);
    float q = -1.45660718464996e-05f;
    q = __fadd_rn(__fmul_rn(q, x2), -2.13374055278905e-04f);
    q = __fadd_rn(__fmul_rn(q, x2), -1.68282697438203e-03f);
    q = __fadd_rn(__fmul_rn(q, x2), -7.37332916720468e-03f);
    q = __fadd_rn(__fmul_rn(q, x2), -1.42647390514189e-02f);
    return __fdiv_rn(__fmul_rn(x, p), q);
}

__device__ __forceinline__ float gelu_f(float v) {
    float t = __fdiv_rn(v, 1.41421356237309504880f);
    float e = erf_xla(t);
    return __fmul_rn(__fmul_rn(v, __fadd_rn(e, 1.0f)), 0.5f);
}

// ---------------------------------------------------------------------------
// LayerNorm (unchanged, passing)
// ---------------------------------------------------------------------------
__global__ void __launch_bounds__(256) ln_kernel(
    const float* __restrict__ x, const float* __restrict__ g,
    const float* __restrict__ b, float* __restrict__ o)
{
    __shared__ double red[8];
    __shared__ float s_mu, s_inv;
    const int row = blockIdx.x;
    const int tid = threadIdx.x;
    const float4* xr = (const float4*)(x + (size_t)row * DMODEL);
    float4* orow = (float4*)(o + (size_t)row * DMODEL);

    float4 v = xr[tid];

    double s = (double)v.x + (double)v.y + (double)v.z + (double)v.w;
    #pragma unroll
    for (int off = 16; off; off >>= 1) s += __shfl_down_sync(0xffffffffu, s, off);
    if ((tid & 31) == 0) red[tid >> 5] = s;
    __syncthreads();
    if (tid == 0) {
        double S = 0.0;
        #pragma unroll
        for (int w = 0; w < 8; w++) S += red[w];
        s_mu = (float)(S * (1.0 / DMODEL));
    }
    __syncthreads();
    const float mu = s_mu;
    __syncthreads();

    float dx0 = __fsub_rn(v.x, mu), dx1 = __fsub_rn(v.y, mu);
    float dx2 = __fsub_rn(v.z, mu), dx3 = __fsub_rn(v.w, mu);
    double ss = (double)__fmul_rn(dx0, dx0) + (double)__fmul_rn(dx1, dx1)
              + (double)__fmul_rn(dx2, dx2) + (double)__fmul_rn(dx3, dx3);
    #pragma unroll
    for (int off = 16; off; off >>= 1) ss += __shfl_down_sync(0xffffffffu, ss, off);
    if ((tid & 31) == 0) red[tid >> 5] = ss;
    __syncthreads();
    if (tid == 0) {
        double SS = 0.0;
        #pragma unroll
        for (int w = 0; w < 8; w++) SS += red[w];
        float var = (float)(SS * (1.0 / DMODEL));
        s_inv = (float)(1.0 / sqrt((double)__fadd_rn(var, 1e-5f)));
    }
    __syncthreads();
    const float inv = s_inv;
    const float4 gv = ((const float4*)g)[tid];
    const float4 bv = ((const float4*)b)[tid];
    float4 r;
    r.x = __fadd_rn(__fmul_rn(__fmul_rn(dx0, inv), gv.x), bv.x);
    r.y = __fadd_rn(__fmul_rn(__fmul_rn(dx1, inv), gv.y), bv.y);
    r.z = __fadd_rn(__fmul_rn(__fmul_rn(dx2, inv), gv.z), bv.z);
    r.w = __fadd_rn(__fmul_rn(__fmul_rn(dx3, inv), gv.w), bv.w);
    orow[tid] = r;
}

// ---------------------------------------------------------------------------
// fp32 -> bf16 hi/lo split
// ---------------------------------------------------------------------------
union bfu { __nv_bfloat162 b; unsigned int u; };

__device__ __forceinline__ void split2(float a, float b, unsigned int& hi, unsigned int& lo) {
    __nv_bfloat16 h0 = __float2bfloat16_rn(a);
    __nv_bfloat16 h1 = __float2bfloat16_rn(b);
    __nv_bfloat16 l0 = __float2bfloat16_rn(__fsub_rn(a, __bfloat162float(h0)));
    __nv_bfloat16 l1 = __float2bfloat16_rn(__fsub_rn(b, __bfloat162float(h1)));
    bfu H; H.b = __nv_bfloat162(h0, h1); hi = H.u;
    bfu L; L.b = __nv_bfloat162(l0, l1); lo = L.u;
}

__global__ void __launch_bounds__(256) split_bf16_kernel(
    const float* __restrict__ src, __nv_bfloat16* __restrict__ hi,
    __nv_bfloat16* __restrict__ lo, size_t n4)
{
    size_t i = (size_t)blockIdx.x * 256 + threadIdx.x;
    size_t stride = (size_t)gridDim.x * 256;
    for (; i < n4; i += stride) {
        float4 v = ((const float4*)src)[i];
        uint2 H, L;
        split2(v.x, v.y, H.x, L.x);
        split2(v.z, v.w, H.y, L.y);
        ((uint2*)hi)[i] = H;
        ((uint2*)lo)[i] = L;
    }
}

__global__ void __launch_bounds__(256) split_bf16_hi_kernel(
    const float* __restrict__ src, __nv_bfloat16* __restrict__ hi, size_t n4)
{
    size_t i = (size_t)blockIdx.x * 256 + threadIdx.x;
    size_t stride = (size_t)gridDim.x * 256;
    for (; i < n4; i += stride) {
        float4 v = ((const float4*)src)[i];
        bfu a, b;
        a.b = __nv_bfloat162(__float2bfloat16_rn(v.x), __float2bfloat16_rn(v.y));
        b.b = __nv_bfloat162(__float2bfloat16_rn(v.z), __float2bfloat16_rn(v.w));
        uint2 H; H.x = a.u; H.y = b.u;
        ((uint2*)hi)[i] = H;
    }
}

// ---------------------------------------------------------------------------
// mma / ldmatrix / cp.async primitives
// ---------------------------------------------------------------------------
__device__ __forceinline__ void mma16_bf16(float c[4], const unsigned int a[4],
                                           const unsigned int b[2]) {
    asm volatile("mma.sync.aligned.m16n8k16.row.col.f32.bf16.bf16.f32 "
        "{%0,%1,%2,%3}, {%4,%5,%6,%7}, {%8,%9}, {%0,%1,%2,%3};\n"
        : "+f"(c[0]), "+f"(c[1]), "+f"(c[2]), "+f"(c[3])
        : "r"(a[0]), "r"(a[1]), "r"(a[2]), "r"(a[3]), "r"(b[0]), "r"(b[1]));
}
__device__ __forceinline__ void ldsm4(unsigned int& r0, unsigned int& r1,
                                      unsigned int& r2, unsigned int& r3,
                                      const void* p) {
    unsigned int a = (unsigned int)__cvta_generic_to_shared(p);
    asm volatile("ldmatrix.sync.aligned.m8n8.x4.shared.b16 {%0,%1,%2,%3}, [%4];"
                 : "=r"(r0), "=r"(r1), "=r"(r2), "=r"(r3) : "r"(a));
}
__device__ __forceinline__ void cpa16(void* s, const void* g) {
    unsigned int a = (unsigned int)__cvta_generic_to_shared(s);
    asm volatile("cp.async.cg.shared.global [%0], [%1], 16;\n"
                 :: "r"(a), "l"(g) : "memory");
}
__device__ __forceinline__ void cpa_commit() {
    asm volatile("cp.async.commit_group;\n" ::: "memory");
}
template <int N>
__device__ __forceinline__ void cpa_wait() {
    asm volatile("cp.async.wait_group %0;\n" :: "n"(N) : "memory");
}

// ---------------------------------------------------------------------------
// bf16 3-term GEMM body, 128x64 tile (proven; used for z in fused_h_z)
// ---------------------------------------------------------------------------
#define STG_STRIDE 18432
#define TC_DYNSMEM (3 * STG_STRIDE)

__device__ __forceinline__ void issue_chunk(
    char* sm, int st, int k0,
    const __nv_bfloat16* Ag0, const __nv_bfloat16* Ag1, const __nv_bfloat16* Bg,
    int arow, int akb, int brow, int bkb, int boff)
{
    char* base = sm + st * STG_STRIDE;
    cpa16(base + arow * 48 + akb,        Ag0 + k0);
    cpa16(base + 6144 + arow * 48 + akb, Ag1 + k0);
    cpa16(base + boff + brow * 48 + bkb, Bg + k0);
    cpa_commit();
}

__device__ __forceinline__ void gemm_bf16_body(
    const __nv_bfloat16* __restrict__ Ahg, const __nv_bfloat16* __restrict__ Alg,
    const __nv_bfloat16* __restrict__ Bhg, const __nv_bfloat16* __restrict__ Blg,
    float* __restrict__ C, int M, int N, int K, int bx, int by, char* sm)
{
    const int tid  = threadIdx.x;
    const int m0   = by * 128;
    const int n0   = bx * 64;
    const int wid  = tid >> 5;
    const int lane = tid & 31;
    const int gid  = lane >> 2;
    const int tig  = lane & 3;
    const int wm   = (wid & 3) * 32;
    const int wn   = (wid >> 2) * 32;
    const int g8   = lane >> 3;
    const int r8   = lane & 7;

    const int arow = tid >> 1, akb = (tid & 1) * 16, ak = (tid & 1) * 8;
    const int bt = tid & 127;
    const int brow = bt >> 1, bkb = (bt & 1) * 16, bk = (bt & 1) * 8;
    const bool bhi = tid < 128;
    const int boff = bhi ? 12288 : 15360;

    const __nv_bfloat16* Ag0 = Ahg + (size_t)(m0 + arow) * K + ak;
    const __nv_bfloat16* Ag1 = Alg + (size_t)(m0 + arow) * K + ak;
    const __nv_bfloat16* Bg  = (bhi ? Bhg : Blg) + (size_t)(n0 + brow) * K + bk;

    float acc[2][4][4];
    #pragma unroll
    for (int mt = 0; mt < 2; mt++)
        #pragma unroll
        for (int nt = 0; nt < 4; nt++)
            #pragma unroll
            for (int r = 0; r < 4; r++) acc[mt][nt][r] = 0.0f;

    const int a_row = wm + (g8 & 1) * 8 + r8;
    const int a_col = (g8 >> 1) * 16;
    const int b_row = wn + (g8 >> 1) * 8 + r8;
    const int b_col = (g8 & 1) * 16;

    const int NC = K >> 4;
    issue_chunk(sm, 0, 0,  Ag0, Ag1, Bg, arow, akb, brow, bkb, boff);
    issue_chunk(sm, 1, 16, Ag0, Ag1, Bg, arow, akb, brow, bkb, boff);

    for (int i = 0; i < NC; i++) {
        const int st = i % 3;
        if (i + 2 < NC) cpa_wait<1>(); else cpa_wait<0>();
        __syncthreads();
        if (i + 2 < NC)
            issue_chunk(sm, (i + 2) % 3, (i + 2) * 16,
                        Ag0, Ag1, Bg, arow, akb, brow, bkb, boff);

        char* base = sm + st * STG_STRIDE;
        unsigned int afh[2][4], afl[2][4], bfh[4][2], bfl[4][2];
        #pragma unroll
        for (int mt = 0; mt < 2; mt++) {
            const int ro = (a_row + mt * 16) * 48 + a_col;
            ldsm4(afh[mt][0], afh[mt][1], afh[mt][2], afh[mt][3], base + ro);
            ldsm4(afl[mt][0], afl[mt][1], afl[mt][2], afl[mt][3], base + 6144 + ro);
        }
        #pragma unroll
        for (int p = 0; p < 2; p++) {
            const int ro = (b_row + p * 16) * 48 + b_col;
            ldsm4(bfh[p*2][0], bfh[p*2][1], bfh[p*2+1][0], bfh[p*2+1][1],
                  base + 12288 + ro);
            ldsm4(bfl[p*2][0], bfl[p*2][1], bfl[p*2+1][0], bfl[p*2+1][1],
                  base + 15360 + ro);
        }
        #pragma unroll
        for (int mt = 0; mt < 2; mt++)
            #pragma unroll
            for (int nt = 0; nt < 4; nt++) {
                mma16_bf16(acc[mt][nt], afh[mt], bfh[nt]);
                mma16_bf16(acc[mt][nt], afh[mt], bfl[nt]);
                mma16_bf16(acc[mt][nt], afl[mt], bfh[nt]);
            }
    }

    #pragma unroll
    for (int mt = 0; mt < 2; mt++)
        #pragma unroll
        for (int nt = 0; nt < 4; nt++) {
            const int r0 = m0 + wm + mt * 16 + gid;
            const int c0 = n0 + wn + nt * 8 + tig * 2;
            *(float2*)&C[(size_t)r0 * N + c0]       = make_float2(acc[mt][nt][0], acc[mt][nt][1]);
            *(float2*)&C[(size_t)(r0 + 8) * N + c0] = make_float2(acc[mt][nt][2], acc[mt][nt][3]);
        }
}

// ---------------------------------------------------------------------------
// NEW: 128x128-tile 3-term GEMM (out). Warp tile 32x64; B frags in 2 halves.
// Stage layout: Ah@0, Al@6144, Bh@12288, Bl@18432; stride 24576.
// K-order and per-k16 term order identical to the 128x64 body -> bit-identical C.
// ---------------------------------------------------------------------------
#define STG_W128 24576
#define DYN_W128 (3 * STG_W128)

__global__ void __launch_bounds__(256) gemm_bt3_w128(
    const __nv_bfloat16* __restrict__ Ahg, const __nv_bfloat16* __restrict__ Alg,
    const __nv_bfloat16* __restrict__ Bhg, const __nv_bfloat16* __restrict__ Blg,
    float* __restrict__ C, int M, int N, int K)
{
    extern __shared__ __align__(16) char sm[];
    const int tid  = threadIdx.x;
    const int m0   = (int)blockIdx.y * 128;
    const int n0   = (int)blockIdx.x * 128;
    const int wid  = tid >> 5;
    const int lane = tid & 31;
    const int gid  = lane >> 2;
    const int tig  = lane & 3;
    const int wm   = (wid & 3) * 32;
    const int wn   = (wid >> 2) * 64;
    const int g8   = lane >> 3;
    const int r8   = lane & 7;

    const int prow = tid >> 1, pkb = (tid & 1) * 16, pk = (tid & 1) * 8;
    const __nv_bfloat16* Ag0 = Ahg + (size_t)(m0 + prow) * K + pk;
    const __nv_bfloat16* Ag1 = Alg + (size_t)(m0 + prow) * K + pk;
    const __nv_bfloat16* Bg0 = Bhg + (size_t)(n0 + prow) * K + pk;
    const __nv_bfloat16* Bg1 = Blg + (size_t)(n0 + prow) * K + pk;

    float acc[2][8][4];
    #pragma unroll
    for (int mt = 0; mt < 2; mt++)
        #pragma unroll
        for (int nt = 0; nt < 8; nt++)
            #pragma unroll
            for (int r = 0; r < 4; r++) acc[mt][nt][r] = 0.0f;

    const int a_row = wm + (g8 & 1) * 8 + r8;
    const int a_col = (g8 >> 1) * 16;
    const int b_row = wn + (g8 >> 1) * 8 + r8;
    const int b_col = (g8 & 1) * 16;

    const int NC = K >> 4;
    #pragma unroll
    for (int pr = 0; pr < 2; pr++) {
        char* base = sm + pr * STG_W128;
        cpa16(base + prow * 48 + pkb,         Ag0 + pr * 16);
        cpa16(base + 6144  + prow * 48 + pkb, Ag1 + pr * 16);
        cpa16(base + 12288 + prow * 48 + pkb, Bg0 + pr * 16);
        cpa16(base + 18432 + prow * 48 + pkb, Bg1 + pr * 16);
        cpa_commit();
    }

    for (int i = 0; i < NC; i++) {
        const int st = i % 3;
        if (i + 2 < NC) cpa_wait<1>(); else cpa_wait<0>();
        __syncthreads();
        if (i + 2 < NC) {
            char* nb = sm + ((i + 2) % 3) * STG_W128;
            const int k0 = (i + 2) * 16;
            cpa16(nb + prow * 48 + pkb,         Ag0 + k0);
            cpa16(nb + 6144  + prow * 48 + pkb, Ag1 + k0);
            cpa16(nb + 12288 + prow * 48 + pkb, Bg0 + k0);
            cpa16(nb + 18432 + prow * 48 + pkb, Bg1 + k0);
            cpa_commit();
        }

        char* base = sm + st * STG_W128;
        unsigned int afh[2][4], afl[2][4];
        #pragma unroll
        for (int mt = 0; mt < 2; mt++) {
            const int ro = (a_row + mt * 16) * 48 + a_col;
            ldsm4(afh[mt][0], afh[mt][1], afh[mt][2], afh[mt][3], base + ro);
            ldsm4(afl[mt][0], afl[mt][1], afl[mt][2], afl[mt][3], base + 6144 + ro);
        }
        #pragma unroll
        for (int half = 0; half < 2; half++) {
            unsigned int bfh[4][2], bfl[4][2];
            #pragma unroll
            for (int p = 0; p < 2; p++) {
                const int ro = (b_row + half * 32 + p * 16) * 48 + b_col;
                ldsm4(bfh[p*2][0], bfh[p*2][1], bfh[p*2+1][0], bfh[p*2+1][1],
                      base + 12288 + ro);
                ldsm4(bfl[p*2][0], bfl[p*2][1], bfl[p*2+1][0], bfl[p*2+1][1],
                      base + 18432 + ro);
            }
            #pragma unroll
            for (int mt = 0; mt < 2; mt++)
                #pragma unroll
                for (int nt = 0; nt < 4; nt++) {
                    mma16_bf16(acc[mt][half*4+nt], afh[mt], bfh[nt]);
                    mma16_bf16(acc[mt][half*4+nt], afh[mt], bfl[nt]);
                    mma16_bf16(acc[mt][half*4+nt], afl[mt], bfh[nt]);
                }
        }
    }

    #pragma unroll
    for (int mt = 0; mt < 2; mt++)
        #pragma unroll
        for (int nt = 0; nt < 8; nt++) {
            const int r0 = m0 + wm + mt * 16 + gid;
            const int c0 = n0 + wn + nt * 8 + tig * 2;
            *(float2*)&C[(size_t)r0 * N + c0]       = make_float2(acc[mt][nt][0], acc[mt][nt][1]);
            *(float2*)&C[(size_t)(r0 + 8) * N + c0] = make_float2(acc[mt][nt][2], acc[mt][nt][3]);
        }
}

// ---------------------------------------------------------------------------
// NEW: 128x128-tile 2-term scores GEMM: C = (Ah+Al) @ Bh^T.
// Stage layout: Ah@0, Al@6144, Bh@12288; stride 18432. Bit-identical values
// to the 128x64 2-term kernel (same k/term order).
// ---------------------------------------------------------------------------
__global__ void __launch_bounds__(256) gemm_sc2_w128(
    const __nv_bfloat16* __restrict__ Ahg, const __nv_bfloat16* __restrict__ Alg,
    const __nv_bfloat16* __restrict__ Bhg,
    float* __restrict__ C, int M, int N, int K)
{
    extern __shared__ __align__(16) char sm[];
    const int tid  = threadIdx.x;
    const int m0   = (int)blockIdx.y * 128;
    const int n0   = (int)blockIdx.x * 128;
    const int wid  = tid >> 5;
    const int lane = tid & 31;
    const int gid  = lane >> 2;
    const int tig  = lane & 3;
    const int wm   = (wid & 3) * 32;
    const int wn   = (wid >> 2) * 64;
    const int g8   = lane >> 3;
    const int r8   = lane & 7;

    const int prow = tid >> 1, pkb = (tid & 1) * 16, pk = (tid & 1) * 8;
    const __nv_bfloat16* Ag0 = Ahg + (size_t)(m0 + prow) * K + pk;
    const __nv_bfloat16* Ag1 = Alg + (size_t)(m0 + prow) * K + pk;
    const __nv_bfloat16* Bg0 = Bhg + (size_t)(n0 + prow) * K + pk;

    float acc[2][8][4];
    #pragma unroll
    for (int mt = 0; mt < 2; mt++)
        #pragma unroll
        for (int nt = 0; nt < 8; nt++)
            #pragma unroll
            for (int r = 0; r < 4; r++) acc[mt][nt][r] = 0.0f;

    const int a_row = wm + (g8 & 1) * 8 + r8;
    const int a_col = (g8 >> 1) * 16;
    const int b_row = wn + (g8 >> 1) * 8 + r8;
    const int b_col = (g8 & 1) * 16;

    const int NC = K >> 4;
    #pragma unroll
    for (int pr = 0; pr < 2; pr++) {
        char* base = sm + pr * STG_STRIDE;
        cpa16(base + prow * 48 + pkb,         Ag0 + pr * 16);
        cpa16(base + 6144  + prow * 48 + pkb, Ag1 + pr * 16);
        cpa16(base + 12288 + prow * 48 + pkb, Bg0 + pr * 16);
        cpa_commit();
    }

    for (int i = 0; i < NC; i++) {
        const int st = i % 3;
        if (i + 2 < NC) cpa_wait<1>(); else cpa_wait<0>();
        __syncthreads();
        if (i + 2 < NC) {
            char* nb = sm + ((i + 2) % 3) * STG_STRIDE;
            const int k0 = (i + 2) * 16;
            cpa16(nb + prow * 48 + pkb,         Ag0 + k0);
            cpa16(nb + 6144  + prow * 48 + pkb, Ag1 + k0);
            cpa16(nb + 12288 + prow * 48 + pkb, Bg0 + k0);
            cpa_commit();
        }

        char* base = sm + st * STG_STRIDE;
        unsigned int afh[2][4], afl[2][4];
        #pragma unroll
        for (int mt = 0; mt < 2; mt++) {
            const int ro = (a_row + mt * 16) * 48 + a_col;
            ldsm4(afh[mt][0], afh[mt][1], afh[mt][2], afh[mt][3], base + ro);
            ldsm4(afl[mt][0], afl[mt][1], afl[mt][2], afl[mt][3], base + 6144 + ro);
        }
        #pragma unroll
        for (int half = 0; half < 2; half++) {
            unsigned int bfh[4][2];
            #pragma unroll
            for (int p = 0; p < 2; p++) {
                const int ro = (b_row + half * 32 + p * 16) * 48 + b_col;
                ldsm4(bfh[p*2][0], bfh[p*2][1], bfh[p*2+1][0], bfh[p*2+1][1],
                      base + 12288 + ro);
            }
            #pragma unroll
            for (int mt = 0; mt < 2; mt++)
                #pragma unroll
                for (int nt = 0; nt < 4; nt++) {
                    mma16_bf16(acc[mt][half*4+nt], afh[mt], bfh[nt]);
                    mma16_bf16(acc[mt][half*4+nt], afl[mt], bfh[nt]);
                }
        }
    }

    #pragma unroll
    for (int mt = 0; mt < 2; mt++)
        #pragma unroll
        for (int nt = 0; nt < 8; nt++) {
            const int r0 = m0 + wm + mt * 16 + gid;
            const int c0 = n0 + wn + nt * 8 + tig * 2;
            *(float2*)&C[(size_t)r0 * N + c0]       = make_float2(acc[mt][nt][0], acc[mt][nt][1]);
            *(float2*)&C[(size_t)(r0 + 8) * N + c0] = make_float2(acc[mt][nt][2], acc[mt][nt][3]);
        }
}

// ---------------------------------------------------------------------------
// fp32 chunked GEMM body for h, with gelu + bf16-split epilogue (unchanged)
// ---------------------------------------------------------------------------
__device__ __forceinline__ void acc_body_h(
    const float* __restrict__ A, const float* __restrict__ B,
    float* __restrict__ C, __nv_bfloat16* __restrict__ Ch,
    __nv_bfloat16* __restrict__ Cl, int M, int N, int K, int bx, int by)
{
    __shared__ float As[8][128];
    __shared__ float Bs[8][64];

    const int m0 = by * 128;
    const int n0 = bx * 64;
    const int tid = threadIdx.x;
    const int lrA = tid >> 1;
    const int lcA = (tid & 1) * 4;
    const int lrB = tid >> 2;
    const int lcB = (tid & 3) * 2;
    const int tx = tid & 15;
    const int ty = tid >> 4;

    const float* Aptr = A + (size_t)(m0 + lrA) * K + lcA;
    const float* Bptr = B + (size_t)(n0 + lrB) * K + lcB;

    float acc[8][4], chk[8][4];
    #pragma unroll
    for (int i = 0; i < 8; i++)
        #pragma unroll
        for (int j = 0; j < 4; j++) { acc[i][j] = 0.0f; chk[i][j] = 0.0f; }

    float4 av = *(const float4*)(Aptr);
    float2 bv = *(const float2*)(Bptr);

    for (int k0 = 0; k0 < K; k0 += 8) {
        As[lcA + 0][lrA] = av.x; As[lcA + 1][lrA] = av.y;
        As[lcA + 2][lrA] = av.z; As[lcA + 3][lrA] = av.w;
        Bs[lcB + 0][lrB] = bv.x; Bs[lcB + 1][lrB] = bv.y;
        __syncthreads();

        if (k0 + 8 < K) {
            av = *(const float4*)(Aptr + k0 + 8);
            bv = *(const float2*)(Bptr + k0 + 8);
        }

        #pragma unroll
        for (int kk = 0; kk < 8; kk++) {
            float4 a0 = *(const float4*)&As[kk][ty * 4];
            float4 a1 = *(const float4*)&As[kk][64 + ty * 4];
            float4 b0 = *(const float4*)&Bs[kk][tx * 4];
            float ar[8] = {a0.x, a0.y, a0.z, a0.w, a1.x, a1.y, a1.z, a1.w};
            float br[4] = {b0.x, b0.y, b0.z, b0.w};
            #pragma unroll
            for (int i = 0; i < 8; i++)
                #pragma unroll
                for (int j = 0; j < 4; j++)
                    chk[i][j] = fmaf(ar[i], br[j], chk[i][j]);
        }
        if ((k0 & 24) == 24) {
            #pragma unroll
            for (int i = 0; i < 8; i++)
                #pragma unroll
                for (int j = 0; j < 4; j++) {
                    acc[i][j] = __fadd_rn(acc[i][j], chk[i][j]);
                    chk[i][j] = 0.0f;
                }
        }
        __syncthreads();
    }

    #pragma unroll
    for (int i = 0; i < 8; i++) {
        const int row = m0 + ((i < 4) ? (ty * 4 + i) : (64 + ty * 4 + i - 4));
        float v0 = gelu_f(acc[i][0]), v1 = gelu_f(acc[i][1]);
        float v2 = gelu_f(acc[i][2]), v3 = gelu_f(acc[i][3]);
        float4 r; r.x = v0; r.y = v1; r.z = v2; r.w = v3;
        *(float4*)(C + (size_t)row * N + n0 + tx * 4) = r;
        unsigned int H0, L0, H1, L1;
        split2(v0, v1, H0, L0);
        split2(v2, v3, H1, L1);
        uint2 H; H.x = H0; H.y = H1;
        uint2 L; L.x = L0; L.y = L1;
        *(uint2*)(Ch + (size_t)row * N + n0 + tx * 4) = H;
        *(uint2*)(Cl + (size_t)row * N + n0 + tx * 4) = L;
    }
}

// ---------------------------------------------------------------------------
// Fused heterogeneous kernel: 1/5 h (fma pipe), 4/5 z (tensor pipe)
// ---------------------------------------------------------------------------
__global__ void __launch_bounds__(256) fused_h_z(
    const float* __restrict__ xn, const float* __restrict__ Wr1,
    float* __restrict__ h, __nv_bfloat16* __restrict__ hh, __nv_bfloat16* __restrict__ hl,
    const __nv_bfloat16* __restrict__ xh, const __nv_bfloat16* __restrict__ xl,
    const __nv_bfloat16* __restrict__ w1h, const __nv_bfloat16* __restrict__ w1l,
    float* __restrict__ z)
{
    extern __shared__ __align__(16) char dynsm[];
    const int bid = blockIdx.x;
    if (bid % 5 == 0) {
        const int sid = bid / 5;
        acc_body_h(xn, Wr1, h, hh, hl, NROWS, DMODEL, DMODEL, sid & 15, sid >> 4);
    } else {
        const int sid = bid - bid / 5 - 1;
        gemm_bf16_body(xh, xl, w1h, w1l, z, NROWS, DFF, DMODEL, sid & 63, sid >> 6, dynsm);
    }
}

// ---------------------------------------------------------------------------
// Hybrid top-k (unchanged from R13, passing)
// ---------------------------------------------------------------------------
__device__ __forceinline__ unsigned int key_map(float f) {
    unsigned int u = __float_as_uint(f);
    return (u & 0x80000000u) ? ~u : (u | 0x80000000u);
}
__device__ __forceinline__ float key_unmap(unsigned int k) {
    unsigned int u = (k & 0x80000000u) ? (k ^ 0x80000000u) : ~k;
    return __uint_as_float(u);
}

#define CAND_CAP 256

__global__ void __launch_bounds__(256) topk_hybrid(
    const float* __restrict__ sc_fast, const float* __restrict__ h,
    const float* __restrict__ Wr2, const float* __restrict__ z,
    __nv_bfloat16* __restrict__ zh, __nv_bfloat16* __restrict__ zl)
{
    __shared__ unsigned int keys[DFF];
    __shared__ unsigned int hist[256];
    __shared__ unsigned char mask[DFF];
    __shared__ int s_nhi, s_ncand;
    __shared__ int s_cidx[CAND_CAP];
    __shared__ float s_cex[CAND_CAP];
    __shared__ float hs[32 * 33];
    __shared__ float chks[2][32];

    const int row = blockIdx.x;
    const int tid = threadIdx.x;
    const int wid = tid >> 5;
    const int lid = tid & 31;
    const float* srow = sc_fast + (size_t)row * DFF;
    const float* zrow = z + (size_t)row * DFF;
    const float* hrow = h + (size_t)row * DMODEL;

    if (tid == 0) { s_nhi = 0; s_ncand = 0; }
    for (int j = tid; j < DFF; j += 256)
        keys[j] = key_map(srow[j]);

    unsigned int prefix = 0, pmask = 0;
    int remaining = TOPK;
    #pragma unroll
    for (int p = 0; p < 4; p++) {
        const int shift = 24 - 8 * p;
        __syncthreads();
        if (tid < 256) hist[tid] = 0;
        __syncthreads();
        for (int j = tid; j < DFF; j += 256) {
            unsigned int k = keys[j];
            if ((k & pmask) == prefix)
                atomicAdd(&hist[(k >> shift) & 255u], 1u);
        }
        __syncthreads();
        int cum = 0, digit = 0;
        for (int bbin = 255; bbin >= 0; bbin--) {
            int c = (int)hist[bbin];
            if (cum + c >= remaining) { digit = bbin; break; }
            cum += c;
        }
        remaining -= cum;
        prefix |= ((unsigned int)digit) << shift;
        pmask  |= 0xFFu << shift;
    }
    const float Tf = key_unmap(prefix);
    const float M = fmaxf(4e-3f, 1e-3f * fabsf(Tf));
    const unsigned int hiK = key_map(Tf + M);
    const unsigned int loK = key_map(Tf - M);

    __syncthreads();
    for (int j = tid; j < DFF; j += 256) {
        unsigned int k = keys[j];
        if (k > hiK) {
            mask[j] = 1;
            atomicAdd(&s_nhi, 1);
        } else {
            mask[j] = 0;
            if (k >= loK) {
                int pos = atomicAdd(&s_ncand, 1);
                if (pos < CAND_CAP) s_cidx[pos] = j;
            }
        }
    }
    __syncthreads();

    const int ncand = min(s_ncand, CAND_CAP);
    const int slots = TOPK - s_nhi;

    for (int i = tid; i < DMODEL; i += 256)
        hs[(i >> 5) * 33 + (i & 31)] = hrow[i];
    float* ws = (float*)keys;
    __syncthreads();

    for (int c0 = 0; c0 < ncand; c0 += 2) {
        const int nc = min(2, ncand - c0);
        for (int q = 0; q < nc; q++) {
            const float* wrow = Wr2 + (size_t)s_cidx[c0 + q] * DMODEL;
            for (int i = tid; i < DMODEL; i += 256)
                ws[q * 2048 + (i >> 5) * 33 + (i & 31)] = wrow[i];
        }
        __syncthreads();
        if (wid < nc) {
            const float* wp = ws + wid * 2048;
            const int b = lid * 33;
            float chk = 0.0f;
            #pragma unroll
            for (int k = 0; k < 32; k++)
                chk = fmaf(hs[b + k], wp[b + k], chk);
            chks[wid][lid] = chk;
            __syncwarp();
            if (lid == 0) {
                float a = 0.0f;
                #pragma unroll
                for (int l = 0; l < 32; l++)
                    a = __fadd_rn(a, chks[wid][l]);
                s_cex[c0 + wid] = a;
            }
        }
        __syncthreads();
    }

    for (int c = tid; c < ncand; c += 256) {
        const float my_s = s_cex[c];
        const int   my_i = s_cidx[c];
        int rank = 0;
        for (int c2 = 0; c2 < ncand; c2++) {
            const float o_s = s_cex[c2];
            if (o_s > my_s || (o_s == my_s && s_cidx[c2] < my_i)) rank++;
        }
        if (rank < slots) mask[my_i] = 1;
    }
    __syncthreads();

    for (int j = tid * 2; j < DFF; j += 512) {
        float v0 = mask[j]     ? gelu_f(zrow[j])     : 0.0f;
        float v1 = mask[j + 1] ? gelu_f(zrow[j + 1]) : 0.0f;
        unsigned int H, L;
        split2(v0, v1, H, L);
        *(unsigned int*)(zh + (size_t)row * DFF + j) = H;
        *(unsigned int*)(zl + (size_t)row * DFF + j) = L;
    }
}

// ---------------------------------------------------------------------------
// Launch
// Inputs: 0:x 1:W1 2:W2 3:W_router_1 4:W_router_2 5:ln_gamma 6:ln_beta 7:top_k
// ---------------------------------------------------------------------------
extern "C" void kernel_launch(void* const* d_in, const int* in_sizes, int n_in,
                              void* d_out, int out_size)
{
    const float* x    = (const float*)d_in[0];
    const float* W1   = (const float*)d_in[1];
    const float* W2   = (const float*)d_in[2];
    const float* Wr1  = (const float*)d_in[3];
    const float* Wr2  = (const float*)d_in[4];
    const float* gma  = (const float*)d_in[5];
    const float* bta  = (const float*)d_in[6];
    float* out = (float*)d_out;

    float *xn, *h, *sc, *z;
    __nv_bfloat16 *xh, *xl, *hh, *hl, *w1h, *w1l, *w2h, *w2l, *wr2h, *zh, *zl;
    cudaGetSymbolAddress((void**)&xn, g_xn);
    cudaGetSymbolAddress((void**)&h,  g_h);
    cudaGetSymbolAddress((void**)&sc, g_sc);
    cudaGetSymbolAddress((void**)&z,  g_z);
    cudaGetSymbolAddress((void**)&xh, g_xh);
    cudaGetSymbolAddress((void**)&xl, g_xl);
    cudaGetSymbolAddress((void**)&hh, g_hh);
    cudaGetSymbolAddress((void**)&hl, g_hl);
    cudaGetSymbolAddress((void**)&w1h, g_w1h);
    cudaGetSymbolAddress((void**)&w1l, g_w1l);
    cudaGetSymbolAddress((void**)&w2h, g_w2h);
    cudaGetSymbolAddress((void**)&w2l, g_w2l);
    cudaGetSymbolAddress((void**)&wr2h, g_wr2h);
    cudaGetSymbolAddress((void**)&zh, g_zh);
    cudaGetSymbolAddress((void**)&zl, g_zl);

    cudaFuncSetAttribute(fused_h_z, cudaFuncAttributeMaxDynamicSharedMemorySize, TC_DYNSMEM);
    cudaFuncSetAttribute(gemm_sc2_w128, cudaFuncAttributeMaxDynamicSharedMemorySize, TC_DYNSMEM);
    cudaFuncSetAttribute(gemm_bt3_w128, cudaFuncAttributeMaxDynamicSharedMemorySize, DYN_W128);

    // 1) xn = LN(x)
    ln_kernel<<<NROWS, 256>>>(x, gma, bta, xn);

    // 1b) bf16 splits: x/W1/W2 hi+lo; Wr2 hi only
    split_bf16_kernel<<<2048, 256>>>(x,   xh,   xl,   (size_t)NROWS * DMODEL / 4);
    split_bf16_kernel<<<1024, 256>>>(W1,  w1h,  w1l,  (size_t)DFF * DMODEL / 4);
    split_bf16_kernel<<<1024, 256>>>(W2,  w2h,  w2l,  (size_t)DMODEL * DFF / 4);
    split_bf16_hi_kernel<<<1024, 256>>>(Wr2, wr2h, (size_t)DFF * DMODEL / 4);

    // 2) fused: h = gelu(xn@Wr1^T) fp32 (fma pipe) ∥ z = x@W1^T bf16 3-term
    fused_h_z<<<10240, 256, TC_DYNSMEM>>>(xn, Wr1, h, hh, hl, xh, xl, w1h, w1l, z);

    // 3) fast scores = (hh+hl) @ wr2h^T — 128x128-tile 2-term kernel
    gemm_sc2_w128<<<dim3(DFF / 128, NROWS / 128), 256, TC_DYNSMEM>>>(
        hh, hl, wr2h, sc, NROWS, DFF, DMODEL);

    // 4) hybrid top-512: margin band + coalesced exact rescore + parallel rank
    topk_hybrid<<<NROWS, 256>>>(sc, h, Wr2, z, zh, zl);

    // 5) out = z @ W2^T — 128x128-tile 3-term kernel
    gemm_bt3_w128<<<dim3(DMODEL / 128, NROWS / 128), 256, DYN_W128>>>(
        zh, zl, w2h, w2l, out, NROWS, DMODEL, DFF);
}